// round 1
// baseline (speedup 1.0000x reference)
#include <cuda_runtime.h>

#define S_TOT 2048
#define DMODEL 3072
#define NHEADS 48
#define HDIM 64
#define RANK_ 128
#define TLEN 226
#define VLEN 1822

// ---------------- scratch (static device memory; no allocations) -----------
__device__ float g_h[S_TOT * DMODEL];
__device__ float g_q[S_TOT * DMODEL];
__device__ float g_k[S_TOT * DMODEL];
__device__ float g_v[S_TOT * DMODEL];
__device__ float g_t[S_TOT * RANK_];
__device__ float g_attn[S_TOT * DMODEL];
__device__ float g_out[S_TOT * DMODEL];

// ---------------- concat(enc, hid) -> g_h ----------------------------------
__global__ void concat_kernel(const float* __restrict__ hid,
                              const float* __restrict__ enc) {
    int i = blockIdx.x * 256 + threadIdx.x;
    if (i >= S_TOT * DMODEL) return;
    int row = i / DMODEL;
    g_h[i] = (row < TLEN) ? enc[i] : hid[i - TLEN * DMODEL];
}

// ---------------- NT GEMM: C[M,N] = A[M,K] @ B[N,K]^T (+bias)(+=C) ---------
// 64x64 tile, BK=32, 256 threads, 4x4 per-thread microtile.
// smem tiles stored transposed [BK][BM+2] so the inner reads are contiguous
// (LDS.64-able) and a-operands broadcast within a warp.
__global__ void __launch_bounds__(256) gemm_nt(
    const float* __restrict__ A, const float* __restrict__ B,
    const float* __restrict__ bias, float* __restrict__ C,
    int M, int N, int K, int accumulate)
{
    __shared__ float As[32][66];
    __shared__ float Bs[32][66];
    int tid = threadIdx.x;
    int ty = tid >> 4, tx = tid & 15;
    int r0 = blockIdx.y << 6, c0 = blockIdx.x << 6;

    float acc[4][4];
#pragma unroll
    for (int i = 0; i < 4; i++)
#pragma unroll
        for (int j = 0; j < 4; j++) acc[i][j] = 0.f;

    const float* Ap = A + (size_t)r0 * K;
    const float* Bp = B + (size_t)c0 * K;

    for (int k0 = 0; k0 < K; k0 += 32) {
#pragma unroll
        for (int i = 0; i < 8; i++) {
            int idx = tid + (i << 8);
            int r = idx >> 5, c = idx & 31;
            As[c][r] = Ap[(size_t)r * K + k0 + c];
            Bs[c][r] = Bp[(size_t)r * K + k0 + c];
        }
        __syncthreads();
#pragma unroll
        for (int kk = 0; kk < 32; kk++) {
            float a[4], b[4];
#pragma unroll
            for (int i = 0; i < 4; i++) a[i] = As[kk][(ty << 2) + i];
#pragma unroll
            for (int j = 0; j < 4; j++) b[j] = Bs[kk][(tx << 2) + j];
#pragma unroll
            for (int i = 0; i < 4; i++)
#pragma unroll
                for (int j = 0; j < 4; j++)
                    acc[i][j] = fmaf(a[i], b[j], acc[i][j]);
        }
        __syncthreads();
    }

#pragma unroll
    for (int i = 0; i < 4; i++) {
        int row = r0 + (ty << 2) + i;
#pragma unroll
        for (int j = 0; j < 4; j++) {
            int col = c0 + (tx << 2) + j;
            float v = acc[i][j];
            if (bias) v += bias[col];
            if (accumulate) v += C[(size_t)row * N + col];
            C[(size_t)row * N + col] = v;
        }
    }
}

// ---------------- per-(pos,head) LayerNorm over 64 dims + RoPE -------------
__global__ void ln_rope_kernel(float* __restrict__ x,
                               const float* __restrict__ gamma,
                               const float* __restrict__ beta,
                               const float* __restrict__ cosb,
                               const float* __restrict__ sinb)
{
    int gw = (blockIdx.x * blockDim.x + threadIdx.x) >> 5;
    int lane = threadIdx.x & 31;
    if (gw >= S_TOT * NHEADS) return;
    int pos = gw / NHEADS, head = gw % NHEADS;
    float* row = x + (size_t)pos * DMODEL + head * HDIM;

    float2 v = ((float2*)row)[lane];
    float sum = v.x + v.y;
#pragma unroll
    for (int o = 16; o; o >>= 1) sum += __shfl_xor_sync(0xffffffffu, sum, o);
    float mu = sum * (1.f / 64.f);
    float dx = v.x - mu, dy = v.y - mu;
    float vs = dx * dx + dy * dy;
#pragma unroll
    for (int o = 16; o; o >>= 1) vs += __shfl_xor_sync(0xffffffffu, vs, o);
    float inv = rsqrtf(vs * (1.f / 64.f) + 1e-5f);

    float y0 = dx * inv * gamma[lane * 2]     + beta[lane * 2];
    float y1 = dy * inv * gamma[lane * 2 + 1] + beta[lane * 2 + 1];

    if (pos >= TLEN) {
        int r = pos - TLEN;
        float c0 = cosb[r * HDIM + lane * 2], c1 = cosb[r * HDIM + lane * 2 + 1];
        float s0 = sinb[r * HDIM + lane * 2], s1 = sinb[r * HDIM + lane * 2 + 1];
        float t0 = y0 * c0 - y1 * s0;   // out[2i]   = x1*cos - x2*sin
        float t1 = y1 * c1 + y0 * s1;   // out[2i+1] = x2*cos + x1*sin
        y0 = t0; y1 = t1;
    }
    ((float2*)row)[lane] = make_float2(y0, y1);
}

// ---------------- flash attention: 1 thread = 1 query row ------------------
__global__ void __launch_bounds__(128) attn_kernel()
{
    const int KT = 16;
    __shared__ float4 Ks[KT][HDIM / 4];
    __shared__ float4 Vs[KT][HDIM / 4];
    int head = blockIdx.y;
    int pos = blockIdx.x * 128 + threadIdx.x;

    const float* qr = g_q + (size_t)pos * DMODEL + head * HDIM;
    float q[HDIM];
#pragma unroll
    for (int d4 = 0; d4 < 16; d4++) {
        float4 t4 = ((const float4*)qr)[d4];
        q[d4 * 4] = t4.x; q[d4 * 4 + 1] = t4.y;
        q[d4 * 4 + 2] = t4.z; q[d4 * 4 + 3] = t4.w;
    }
    float o[HDIM];
#pragma unroll
    for (int d = 0; d < HDIM; d++) o[d] = 0.f;
    float m = -3.0e38f, l = 0.f;

    for (int k0 = 0; k0 < S_TOT; k0 += KT) {
        __syncthreads();
#pragma unroll
        for (int i = 0; i < 2; i++) {
            int idx = threadIdx.x + i * 128;   // 256 float4s per matrix
            int kr = idx >> 4, kd = idx & 15;
            Ks[kr][kd] = ((const float4*)(g_k + (size_t)(k0 + kr) * DMODEL + head * HDIM))[kd];
            Vs[kr][kd] = ((const float4*)(g_v + (size_t)(k0 + kr) * DMODEL + head * HDIM))[kd];
        }
        __syncthreads();

        float s[KT];
#pragma unroll
        for (int j = 0; j < KT; j++) {
            float acc = 0.f;
#pragma unroll
            for (int d4 = 0; d4 < 16; d4++) {
                float4 kv = Ks[j][d4];
                acc = fmaf(q[d4 * 4],     kv.x, acc);
                acc = fmaf(q[d4 * 4 + 1], kv.y, acc);
                acc = fmaf(q[d4 * 4 + 2], kv.z, acc);
                acc = fmaf(q[d4 * 4 + 3], kv.w, acc);
            }
            s[j] = acc * 0.125f;   // 1/sqrt(64)
        }
        float tmax = s[0];
#pragma unroll
        for (int j = 1; j < KT; j++) tmax = fmaxf(tmax, s[j]);
        float mn = fmaxf(m, tmax);
        float corr = __expf(m - mn);
        l *= corr;
#pragma unroll
        for (int d = 0; d < HDIM; d++) o[d] *= corr;
#pragma unroll
        for (int j = 0; j < KT; j++) {
            float p = __expf(s[j] - mn);
            l += p;
#pragma unroll
            for (int d4 = 0; d4 < 16; d4++) {
                float4 vv = Vs[j][d4];
                o[d4 * 4]     = fmaf(p, vv.x, o[d4 * 4]);
                o[d4 * 4 + 1] = fmaf(p, vv.y, o[d4 * 4 + 1]);
                o[d4 * 4 + 2] = fmaf(p, vv.z, o[d4 * 4 + 2]);
                o[d4 * 4 + 3] = fmaf(p, vv.w, o[d4 * 4 + 3]);
            }
        }
        m = mn;
    }

    float inv = 1.f / l;
    float* outr = g_attn + (size_t)pos * DMODEL + head * HDIM;
#pragma unroll
    for (int d4 = 0; d4 < 16; d4++) {
        ((float4*)outr)[d4] = make_float4(o[d4 * 4] * inv, o[d4 * 4 + 1] * inv,
                                          o[d4 * 4 + 2] * inv, o[d4 * 4 + 3] * inv);
    }
}

// ---------------- row permute into d_out: [hid_out | enc_out] --------------
__global__ void permute_kernel(float* __restrict__ out) {
    int i = blockIdx.x * 256 + threadIdx.x;
    if (i >= S_TOT * DMODEL) return;
    int row = i / DMODEL;
    if (row < TLEN) out[(size_t)VLEN * DMODEL + i] = g_out[i];
    else            out[i - TLEN * DMODEL] = g_out[i];
}

// ---------------------------------------------------------------------------
extern "C" void kernel_launch(void* const* d_in, const int* in_sizes, int n_in,
                              void* d_out, int out_size)
{
    const float* hid = (const float*)d_in[0];
    const float* enc = (const float*)d_in[1];
    const float* rc  = (const float*)d_in[2];
    const float* rs  = (const float*)d_in[3];
    const float* Wq  = (const float*)d_in[4];  const float* bq = (const float*)d_in[5];
    const float* Wk  = (const float*)d_in[6];  const float* bk = (const float*)d_in[7];
    const float* Wv  = (const float*)d_in[8];  const float* bv = (const float*)d_in[9];
    const float* Wo  = (const float*)d_in[10]; const float* bo = (const float*)d_in[11];
    const float* lqd = (const float*)d_in[12]; const float* lqu = (const float*)d_in[13];
    const float* lkd = (const float*)d_in[14]; const float* lku = (const float*)d_in[15];
    const float* lvd = (const float*)d_in[16]; const float* lvu = (const float*)d_in[17];
    const float* lpd = (const float*)d_in[18]; const float* lpu = (const float*)d_in[19];
    const float* gq  = (const float*)d_in[20]; const float* btq = (const float*)d_in[21];
    const float* gk  = (const float*)d_in[22]; const float* btk = (const float*)d_in[23];

    float *ph, *pq, *pk, *pv, *pt, *pa, *po;
    cudaGetSymbolAddress((void**)&ph, g_h);
    cudaGetSymbolAddress((void**)&pq, g_q);
    cudaGetSymbolAddress((void**)&pk, g_k);
    cudaGetSymbolAddress((void**)&pv, g_v);
    cudaGetSymbolAddress((void**)&pt, g_t);
    cudaGetSymbolAddress((void**)&pa, g_attn);
    cudaGetSymbolAddress((void**)&po, g_out);

    dim3 big_grid(DMODEL / 64, S_TOT / 64);
    dim3 lora_grid(RANK_ / 64, S_TOT / 64);
    int nelem_blocks = (S_TOT * DMODEL + 255) / 256;

    concat_kernel<<<nelem_blocks, 256>>>(hid, enc);

    // Q = h@Wq^T + bq + (h@lqd^T)@lqu^T
    gemm_nt<<<lora_grid, 256>>>(ph, lqd, nullptr, pt, S_TOT, RANK_, DMODEL, 0);
    gemm_nt<<<big_grid, 256>>>(ph, Wq, bq, pq, S_TOT, DMODEL, DMODEL, 0);
    gemm_nt<<<big_grid, 256>>>(pt, lqu, nullptr, pq, S_TOT, DMODEL, RANK_, 1);
    // K
    gemm_nt<<<lora_grid, 256>>>(ph, lkd, nullptr, pt, S_TOT, RANK_, DMODEL, 0);
    gemm_nt<<<big_grid, 256>>>(ph, Wk, bk, pk, S_TOT, DMODEL, DMODEL, 0);
    gemm_nt<<<big_grid, 256>>>(pt, lku, nullptr, pk, S_TOT, DMODEL, RANK_, 1);
    // V
    gemm_nt<<<lora_grid, 256>>>(ph, lvd, nullptr, pt, S_TOT, RANK_, DMODEL, 0);
    gemm_nt<<<big_grid, 256>>>(ph, Wv, bv, pv, S_TOT, DMODEL, DMODEL, 0);
    gemm_nt<<<big_grid, 256>>>(pt, lvu, nullptr, pv, S_TOT, DMODEL, RANK_, 1);

    // LN(+RoPE for pos >= TLEN) on q, k
    int ln_blocks = (S_TOT * NHEADS * 32 + 255) / 256;
    ln_rope_kernel<<<ln_blocks, 256>>>(pq, gq, btq, rc, rs);
    ln_rope_kernel<<<ln_blocks, 256>>>(pk, gk, btk, rc, rs);

    // attention
    attn_kernel<<<dim3(S_TOT / 128, NHEADS), 128>>>();

    // out = attn@Wo^T + bo + (attn@lpd^T)@lpu^T
    gemm_nt<<<lora_grid, 256>>>(pa, lpd, nullptr, pt, S_TOT, RANK_, DMODEL, 0);
    gemm_nt<<<big_grid, 256>>>(pa, Wo, bo, po, S_TOT, DMODEL, DMODEL, 0);
    gemm_nt<<<big_grid, 256>>>(pt, lpu, nullptr, po, S_TOT, DMODEL, RANK_, 1);

    permute_kernel<<<nelem_blocks, 256>>>((float*)d_out);
}

// round 3
// speedup vs baseline: 1.8730x; 1.8730x over previous
#include <cuda_runtime.h>
#include <cuda_bf16.h>
#include <cstdint>

#define S_TOT 2048
#define DMODEL 3072
#define NHEADS 48
#define HDIM 64
#define RANK_ 128
#define TLEN 226
#define VLEN 1822

#define K3 (3 * DMODEL)       // 9216: split width of D
#define KR3 (3 * RANK_)       // 384:  split width of rank
#define LDAB (K3 + KR3)       // 9600: fused A / W operand width

// ---------------- fp32 scratch ----------------------------------------------
__device__ __align__(256) float g_q[S_TOT * DMODEL];
__device__ __align__(256) float g_k[S_TOT * DMODEL];
__device__ __align__(256) float g_v[S_TOT * DMODEL];
__device__ __align__(256) float g_t[S_TOT * RANK_];
__device__ __align__(256) float g_attn[S_TOT * DMODEL];
__device__ __align__(256) float g_out[S_TOT * DMODEL];

// ---------------- bf16 split operand buffers ---------------------------------
__device__ __align__(256) __nv_bfloat16 g_ab[(size_t)S_TOT * LDAB];   // [h-split | t-split]
__device__ __align__(256) __nv_bfloat16 g_wb[(size_t)DMODEL * LDAB];  // [W-split | lu-split]
__device__ __align__(256) __nv_bfloat16 g_ldb[(size_t)RANK_ * K3];    // lora-down weight split

// ============================================================================
// helpers
// ============================================================================
__device__ __forceinline__ uint32_t s2u(const void* p) {
    return (uint32_t)__cvta_generic_to_shared(p);
}
__device__ __forceinline__ void cpa16(uint32_t s, const void* g) {
    asm volatile("cp.async.cg.shared.global [%0], [%1], 16;" :: "r"(s), "l"(g));
}
__device__ __forceinline__ void ldsm4(uint32_t* r, uint32_t a) {
    asm volatile("ldmatrix.sync.aligned.m8n8.x4.shared.b16 {%0,%1,%2,%3}, [%4];"
                 : "=r"(r[0]), "=r"(r[1]), "=r"(r[2]), "=r"(r[3]) : "r"(a));
}
__device__ __forceinline__ void ldsm2(uint32_t* r, uint32_t a) {
    asm volatile("ldmatrix.sync.aligned.m8n8.x2.shared.b16 {%0,%1}, [%2];"
                 : "=r"(r[0]), "=r"(r[1]) : "r"(a));
}
__device__ __forceinline__ void mma_bf16(float* c, const uint32_t* a, const uint32_t* b) {
    asm volatile(
        "mma.sync.aligned.m16n8k16.row.col.f32.bf16.bf16.f32 "
        "{%0,%1,%2,%3}, {%4,%5,%6,%7}, {%8,%9}, {%0,%1,%2,%3};"
        : "+f"(c[0]), "+f"(c[1]), "+f"(c[2]), "+f"(c[3])
        : "r"(a[0]), "r"(a[1]), "r"(a[2]), "r"(a[3]), "r"(b[0]), "r"(b[1]));
}

// ============================================================================
// split kernels: fp32 -> bf16 (hi, lo) triplets.
//   amode: [hi, lo, hi]   bmode: [hi, hi, lo]
// ============================================================================
__global__ void split_kernel(const float* __restrict__ src,
                             __nv_bfloat16* __restrict__ dst,
                             int K, int dstStride, int dstOff, int amode, int n)
{
    int i = blockIdx.x * 256 + threadIdx.x;
    if (i >= n) return;
    int r = i / K, k = i % K;
    float x = src[i];
    __nv_bfloat16 hi = __float2bfloat16(x);
    __nv_bfloat16 lo = __float2bfloat16(x - __bfloat162float(hi));
    __nv_bfloat16* d = dst + (size_t)r * dstStride + dstOff;
    d[k] = hi;
    d[K + k] = amode ? lo : hi;
    d[2 * K + k] = amode ? hi : lo;
}

// fused concat(enc,hid) + A-split into g_ab cols [0, K3)
__global__ void split_concat_kernel(const float* __restrict__ hid,
                                    const float* __restrict__ enc)
{
    int i = blockIdx.x * 256 + threadIdx.x;
    if (i >= S_TOT * DMODEL) return;
    int r = i / DMODEL, k = i % DMODEL;
    float x = (r < TLEN) ? enc[i] : hid[i - TLEN * DMODEL];
    __nv_bfloat16 hi = __float2bfloat16(x);
    __nv_bfloat16 lo = __float2bfloat16(x - __bfloat162float(hi));
    __nv_bfloat16* d = g_ab + (size_t)r * LDAB;
    d[k] = hi;
    d[DMODEL + k] = lo;
    d[2 * DMODEL + k] = hi;
}

// ============================================================================
// HMMA NT GEMM: C[M,N] = A[M,*] @ B[N,*]^T over K = chunks*32 bf16 cols
// 128x128 CTA tile, BK=32, 256 thr (8 warps, 2x4), warp tile 64x32,
// double-buffered cp.async, m16n8k16 bf16 mma, fp32 accum.
// grid = (N/128, M/128, ksplit); ksplit>1 => atomicAdd epilogue.
// ============================================================================
__global__ void __launch_bounds__(256) gemm_hmma(
    const __nv_bfloat16* __restrict__ A, int lda,
    const __nv_bfloat16* __restrict__ B, int ldb,
    const float* __restrict__ bias, float* __restrict__ C, int ldc,
    int chunks, int use_atomic)
{
    __shared__ __align__(16) __nv_bfloat16 smA[2][128 * 40];
    __shared__ __align__(16) __nv_bfloat16 smB[2][128 * 40];

    const int tid = threadIdx.x;
    const int lane = tid & 31;
    const int wid = tid >> 5;
    const int wm0 = (wid & 1) * 64;
    const int wn0 = (wid >> 1) * 32;
    const int r0 = blockIdx.y << 7;
    const int c0 = blockIdx.x << 7;
    const int kbase = blockIdx.z * chunks * 32;

    float acc[4][4][4];
#pragma unroll
    for (int i = 0; i < 4; i++)
#pragma unroll
        for (int j = 0; j < 4; j++)
#pragma unroll
            for (int e = 0; e < 4; e++) acc[i][j][e] = 0.f;

    const int lrow = tid >> 2;          // 0..63
    const int lpart = tid & 3;          // 0..3
    const __nv_bfloat16* Ag = A + (size_t)(r0 + lrow) * lda + kbase + lpart * 8;
    const __nv_bfloat16* Bg = B + (size_t)(c0 + lrow) * ldb + kbase + lpart * 8;
    const size_t a64 = (size_t)64 * lda;   // +64 rows
    const size_t b64 = (size_t)64 * ldb;

    auto load_tile = [&](int c) {
        int b = c & 1;
        uint32_t sa = s2u(&smA[b][0]) + lrow * 80 + lpart * 16;
        uint32_t sb = s2u(&smB[b][0]) + lrow * 80 + lpart * 16;
        const __nv_bfloat16* ga = Ag + c * 32;
        const __nv_bfloat16* gb = Bg + c * 32;
        cpa16(sa, ga);
        cpa16(sa + 64 * 80, ga + a64);
        cpa16(sb, gb);
        cpa16(sb + 64 * 80, gb + b64);
        asm volatile("cp.async.commit_group;" ::: "memory");
    };

    load_tile(0);

    for (int c = 0; c < chunks; c++) {
        if (c + 1 < chunks) {
            load_tile(c + 1);
            asm volatile("cp.async.wait_group 1;" ::: "memory");
        } else {
            asm volatile("cp.async.wait_group 0;" ::: "memory");
        }
        __syncthreads();

        int b = c & 1;
        uint32_t saw = s2u(&smA[b][0]) + (uint32_t)((wm0 + (lane & 15)) * 80)
                       + ((lane >> 4) << 4);
        uint32_t sbw = s2u(&smB[b][0]) + (uint32_t)((wn0 + (lane & 7)) * 80)
                       + (((lane >> 3) & 1) << 4);
#pragma unroll
        for (int s = 0; s < 2; s++) {
            uint32_t af[4][4], bf[4][2];
#pragma unroll
            for (int i = 0; i < 4; i++) ldsm4(af[i], saw + i * (16 * 80) + s * 32);
#pragma unroll
            for (int j = 0; j < 4; j++) ldsm2(bf[j], sbw + j * (8 * 80) + s * 32);
#pragma unroll
            for (int i = 0; i < 4; i++)
#pragma unroll
                for (int j = 0; j < 4; j++)
                    mma_bf16(acc[i][j], af[i], bf[j]);
        }
        __syncthreads();
    }

    // epilogue
#pragma unroll
    for (int i = 0; i < 4; i++) {
#pragma unroll
        for (int j = 0; j < 4; j++) {
            int mm = r0 + wm0 + i * 16 + (lane >> 2);
            int nn = c0 + wn0 + j * 8 + (lane & 3) * 2;
            float* p0 = C + (size_t)mm * ldc + nn;
            float* p1 = C + (size_t)(mm + 8) * ldc + nn;
            if (use_atomic) {
                atomicAdd(p0,     acc[i][j][0]);
                atomicAdd(p0 + 1, acc[i][j][1]);
                atomicAdd(p1,     acc[i][j][2]);
                atomicAdd(p1 + 1, acc[i][j][3]);
            } else {
                float b0v = bias ? bias[nn] : 0.f;
                float b1v = bias ? bias[nn + 1] : 0.f;
                p0[0] = acc[i][j][0] + b0v;
                p0[1] = acc[i][j][1] + b1v;
                p1[0] = acc[i][j][2] + b0v;
                p1[1] = acc[i][j][3] + b1v;
            }
        }
    }
}

// ============================================================================
// LayerNorm(64) + RoPE
// ============================================================================
__global__ void ln_rope_kernel(float* __restrict__ x,
                               const float* __restrict__ gamma,
                               const float* __restrict__ beta,
                               const float* __restrict__ cosb,
                               const float* __restrict__ sinb)
{
    int gw = (blockIdx.x * blockDim.x + threadIdx.x) >> 5;
    int lane = threadIdx.x & 31;
    if (gw >= S_TOT * NHEADS) return;
    int pos = gw / NHEADS, head = gw % NHEADS;
    float* row = x + (size_t)pos * DMODEL + head * HDIM;

    float2 v = ((float2*)row)[lane];
    float sum = v.x + v.y;
#pragma unroll
    for (int o = 16; o; o >>= 1) sum += __shfl_xor_sync(0xffffffffu, sum, o);
    float mu = sum * (1.f / 64.f);
    float dx = v.x - mu, dy = v.y - mu;
    float vs = dx * dx + dy * dy;
#pragma unroll
    for (int o = 16; o; o >>= 1) vs += __shfl_xor_sync(0xffffffffu, vs, o);
    float inv = rsqrtf(vs * (1.f / 64.f) + 1e-5f);

    float y0 = dx * inv * gamma[lane * 2]     + beta[lane * 2];
    float y1 = dy * inv * gamma[lane * 2 + 1] + beta[lane * 2 + 1];

    if (pos >= TLEN) {
        int r = pos - TLEN;
        float c0 = cosb[r * HDIM + lane * 2], c1 = cosb[r * HDIM + lane * 2 + 1];
        float s0 = sinb[r * HDIM + lane * 2], s1 = sinb[r * HDIM + lane * 2 + 1];
        float t0 = y0 * c0 - y1 * s0;
        float t1 = y1 * c1 + y0 * s1;
        y0 = t0; y1 = t1;
    }
    ((float2*)row)[lane] = make_float2(y0, y1);
}

// ============================================================================
// flash attention: 1 thread = 1 query row (fp32)
// ============================================================================
__global__ void __launch_bounds__(128) attn_kernel()
{
    const int KT = 16;
    __shared__ float4 Ks[KT][HDIM / 4];
    __shared__ float4 Vs[KT][HDIM / 4];
    int head = blockIdx.y;
    int pos = blockIdx.x * 128 + threadIdx.x;

    const float* qr = g_q + (size_t)pos * DMODEL + head * HDIM;
    float q[HDIM];
#pragma unroll
    for (int d4 = 0; d4 < 16; d4++) {
        float4 t4 = ((const float4*)qr)[d4];
        q[d4 * 4] = t4.x; q[d4 * 4 + 1] = t4.y;
        q[d4 * 4 + 2] = t4.z; q[d4 * 4 + 3] = t4.w;
    }
    float o[HDIM];
#pragma unroll
    for (int d = 0; d < HDIM; d++) o[d] = 0.f;
    float m = -3.0e38f, l = 0.f;

    for (int k0 = 0; k0 < S_TOT; k0 += KT) {
        __syncthreads();
#pragma unroll
        for (int i = 0; i < 2; i++) {
            int idx = threadIdx.x + i * 128;
            int kr = idx >> 4, kd = idx & 15;
            Ks[kr][kd] = ((const float4*)(g_k + (size_t)(k0 + kr) * DMODEL + head * HDIM))[kd];
            Vs[kr][kd] = ((const float4*)(g_v + (size_t)(k0 + kr) * DMODEL + head * HDIM))[kd];
        }
        __syncthreads();

        float s[KT];
#pragma unroll
        for (int j = 0; j < KT; j++) {
            float accq = 0.f;
#pragma unroll
            for (int d4 = 0; d4 < 16; d4++) {
                float4 kv = Ks[j][d4];
                accq = fmaf(q[d4 * 4],     kv.x, accq);
                accq = fmaf(q[d4 * 4 + 1], kv.y, accq);
                accq = fmaf(q[d4 * 4 + 2], kv.z, accq);
                accq = fmaf(q[d4 * 4 + 3], kv.w, accq);
            }
            s[j] = accq * 0.125f;
        }
        float tmax = s[0];
#pragma unroll
        for (int j = 1; j < KT; j++) tmax = fmaxf(tmax, s[j]);
        float mn = fmaxf(m, tmax);
        float corr = __expf(m - mn);
        l *= corr;
#pragma unroll
        for (int d = 0; d < HDIM; d++) o[d] *= corr;
#pragma unroll
        for (int j = 0; j < KT; j++) {
            float p = __expf(s[j] - mn);
            l += p;
#pragma unroll
            for (int d4 = 0; d4 < 16; d4++) {
                float4 vv = Vs[j][d4];
                o[d4 * 4]     = fmaf(p, vv.x, o[d4 * 4]);
                o[d4 * 4 + 1] = fmaf(p, vv.y, o[d4 * 4 + 1]);
                o[d4 * 4 + 2] = fmaf(p, vv.z, o[d4 * 4 + 2]);
                o[d4 * 4 + 3] = fmaf(p, vv.w, o[d4 * 4 + 3]);
            }
        }
        m = mn;
    }

    float inv = 1.f / l;
    float* outr = g_attn + (size_t)pos * DMODEL + head * HDIM;
#pragma unroll
    for (int d4 = 0; d4 < 16; d4++) {
        ((float4*)outr)[d4] = make_float4(o[d4 * 4] * inv, o[d4 * 4 + 1] * inv,
                                          o[d4 * 4 + 2] * inv, o[d4 * 4 + 3] * inv);
    }
}

// ---------------- row permute into d_out: [hid_out | enc_out] ---------------
__global__ void permute_kernel(float* __restrict__ out) {
    int i = blockIdx.x * 256 + threadIdx.x;
    if (i >= S_TOT * DMODEL) return;
    int row = i / DMODEL;
    if (row < TLEN) out[(size_t)VLEN * DMODEL + i] = g_out[i];
    else            out[i - TLEN * DMODEL] = g_out[i];
}

// ============================================================================
extern "C" void kernel_launch(void* const* d_in, const int* in_sizes, int n_in,
                              void* d_out, int out_size)
{
    const float* hid = (const float*)d_in[0];
    const float* enc = (const float*)d_in[1];
    const float* rc  = (const float*)d_in[2];
    const float* rs  = (const float*)d_in[3];
    const float* Wq  = (const float*)d_in[4];  const float* bq = (const float*)d_in[5];
    const float* Wk  = (const float*)d_in[6];  const float* bk = (const float*)d_in[7];
    const float* Wv  = (const float*)d_in[8];  const float* bv = (const float*)d_in[9];
    const float* Wo  = (const float*)d_in[10]; const float* bo = (const float*)d_in[11];
    const float* lqd = (const float*)d_in[12]; const float* lqu = (const float*)d_in[13];
    const float* lkd = (const float*)d_in[14]; const float* lku = (const float*)d_in[15];
    const float* lvd = (const float*)d_in[16]; const float* lvu = (const float*)d_in[17];
    const float* lpd = (const float*)d_in[18]; const float* lpu = (const float*)d_in[19];
    const float* gq  = (const float*)d_in[20]; const float* btq = (const float*)d_in[21];
    const float* gk  = (const float*)d_in[22]; const float* btk = (const float*)d_in[23];

    float *pq, *pk, *pv, *pt, *pa, *po;
    __nv_bfloat16 *pab, *pwb, *pldb;
    cudaGetSymbolAddress((void**)&pq, g_q);
    cudaGetSymbolAddress((void**)&pk, g_k);
    cudaGetSymbolAddress((void**)&pv, g_v);
    cudaGetSymbolAddress((void**)&pt, g_t);
    cudaGetSymbolAddress((void**)&pa, g_attn);
    cudaGetSymbolAddress((void**)&po, g_out);
    cudaGetSymbolAddress((void**)&pab, g_ab);
    cudaGetSymbolAddress((void**)&pwb, g_wb);
    cudaGetSymbolAddress((void**)&pldb, g_ldb);

    const int nHD = S_TOT * DMODEL;
    const int nW  = DMODEL * DMODEL;
    const int nLD = RANK_ * DMODEL;
    const int nLU = DMODEL * RANK_;
    const int nT  = S_TOT * RANK_;

    dim3 big_grid(DMODEL / 128, S_TOT / 128, 1);   // 24 x 16
    dim3 lora_grid(1, S_TOT / 128, 8);             // split-K = 8, 36 chunks each
    const int BIG_CH = LDAB / 32;                  // 300
    const int LORA_CH = (K3 / 32) / 8;             // 36

    // A operand for q/k/v projections: concat+split of h
    split_concat_kernel<<<(nHD + 255) / 256, 256>>>(hid, enc);

    struct Proj { const float* W; const float* b; const float* ld; const float* lu; float* out; };
    Proj projs[3] = { {Wq, bq, lqd, lqu, pq}, {Wk, bk, lkd, lku, pk}, {Wv, bv, lvd, lvu, pv} };

    for (int p = 0; p < 3; p++) {
        // weight splits
        split_kernel<<<(nW + 255) / 256, 256>>>(projs[p].W, pwb, DMODEL, LDAB, 0, 0, nW);
        split_kernel<<<(nLU + 255) / 256, 256>>>(projs[p].lu, pwb, RANK_, LDAB, K3, 0, nLU);
        split_kernel<<<(nLD + 255) / 256, 256>>>(projs[p].ld, pldb, DMODEL, K3, 0, 0, nLD);
        // lora-down: t = h @ ld^T  (split-K atomic)
        cudaMemsetAsync(pt, 0, nT * sizeof(float));
        gemm_hmma<<<lora_grid, 256>>>(pab, LDAB, pldb, K3, nullptr, pt, RANK_, LORA_CH, 1);
        // t split into A operand tail
        split_kernel<<<(nT + 255) / 256, 256>>>(pt, pab, RANK_, LDAB, K3, 1, nT);
        // fused main + lora-up GEMM
        gemm_hmma<<<big_grid, 256>>>(pab, LDAB, pwb, LDAB, projs[p].b, projs[p].out,
                                     DMODEL, BIG_CH, 0);
    }

    // LN + RoPE on q, k
    int ln_blocks = (S_TOT * NHEADS * 32 + 255) / 256;
    ln_rope_kernel<<<ln_blocks, 256>>>(pq, gq, btq, rc, rs);
    ln_rope_kernel<<<ln_blocks, 256>>>(pk, gk, btk, rc, rs);

    // attention
    attn_kernel<<<dim3(S_TOT / 128, NHEADS), 128>>>();

    // output projection (A operand = attn out)
    split_kernel<<<(nHD + 255) / 256, 256>>>(pa, pab, DMODEL, LDAB, 0, 1, nHD);
    split_kernel<<<(nW + 255) / 256, 256>>>(Wo, pwb, DMODEL, LDAB, 0, 0, nW);
    split_kernel<<<(nLU + 255) / 256, 256>>>(lpu, pwb, RANK_, LDAB, K3, 0, nLU);
    split_kernel<<<(nLD + 255) / 256, 256>>>(lpd, pldb, DMODEL, K3, 0, 0, nLD);
    cudaMemsetAsync(pt, 0, nT * sizeof(float));
    gemm_hmma<<<lora_grid, 256>>>(pab, LDAB, pldb, K3, nullptr, pt, RANK_, LORA_CH, 1);
    split_kernel<<<(nT + 255) / 256, 256>>>(pt, pab, RANK_, LDAB, K3, 1, nT);
    gemm_hmma<<<big_grid, 256>>>(pab, LDAB, pwb, LDAB, bo, po, DMODEL, BIG_CH, 0);

    permute_kernel<<<(nHD + 255) / 256, 256>>>((float*)d_out);
}

// round 4
// speedup vs baseline: 3.1311x; 1.6717x over previous
#include <cuda_runtime.h>
#include <cuda_bf16.h>
#include <cstdint>

#define S_TOT 2048
#define DMODEL 3072
#define NHEADS 48
#define HDIM 64
#define RANK_ 128
#define TLEN 226
#define VLEN 1822

#define K3 (3 * DMODEL)       // 9216
#define KR3 (3 * RANK_)       // 384
#define LDAB (K3 + KR3)       // 9600

// ---------------- fp32 scratch ----------------------------------------------
__device__ __align__(256) float g_q[S_TOT * DMODEL];
__device__ __align__(256) float g_k[S_TOT * DMODEL];
__device__ __align__(256) float g_v[S_TOT * DMODEL];
__device__ __align__(256) float g_t[S_TOT * RANK_];
__device__ __align__(256) float g_attn[S_TOT * DMODEL];
__device__ __align__(256) float g_out[S_TOT * DMODEL];

// ---------------- bf16 split operand buffers ---------------------------------
__device__ __align__(256) __nv_bfloat16 g_ab[(size_t)S_TOT * LDAB];
__device__ __align__(256) __nv_bfloat16 g_wb[(size_t)DMODEL * LDAB];
__device__ __align__(256) __nv_bfloat16 g_ldb[(size_t)RANK_ * K3];

// ---------------- attention split planes (head-major) -----------------------
__device__ __align__(256) __nv_bfloat16 g_qhi[(size_t)NHEADS * S_TOT * HDIM];
__device__ __align__(256) __nv_bfloat16 g_qlo[(size_t)NHEADS * S_TOT * HDIM];
__device__ __align__(256) __nv_bfloat16 g_khi[(size_t)NHEADS * S_TOT * HDIM];
__device__ __align__(256) __nv_bfloat16 g_klo[(size_t)NHEADS * S_TOT * HDIM];
__device__ __align__(256) __nv_bfloat16 g_vthi[(size_t)NHEADS * HDIM * S_TOT];
__device__ __align__(256) __nv_bfloat16 g_vtlo[(size_t)NHEADS * HDIM * S_TOT];

// ============================================================================
// helpers
// ============================================================================
__device__ __forceinline__ uint32_t s2u(const void* p) {
    return (uint32_t)__cvta_generic_to_shared(p);
}
__device__ __forceinline__ void cpa16(uint32_t s, const void* g) {
    asm volatile("cp.async.cg.shared.global [%0], [%1], 16;" :: "r"(s), "l"(g));
}
__device__ __forceinline__ void cpa_commit() {
    asm volatile("cp.async.commit_group;" ::: "memory");
}
__device__ __forceinline__ void ldsm4(uint32_t* r, uint32_t a) {
    asm volatile("ldmatrix.sync.aligned.m8n8.x4.shared.b16 {%0,%1,%2,%3}, [%4];"
                 : "=r"(r[0]), "=r"(r[1]), "=r"(r[2]), "=r"(r[3]) : "r"(a));
}
__device__ __forceinline__ void ldsm2(uint32_t* r, uint32_t a) {
    asm volatile("ldmatrix.sync.aligned.m8n8.x2.shared.b16 {%0,%1}, [%2];"
                 : "=r"(r[0]), "=r"(r[1]) : "r"(a));
}
__device__ __forceinline__ void mma_bf16(float* c, const uint32_t* a, const uint32_t* b) {
    asm volatile(
        "mma.sync.aligned.m16n8k16.row.col.f32.bf16.bf16.f32 "
        "{%0,%1,%2,%3}, {%4,%5,%6,%7}, {%8,%9}, {%0,%1,%2,%3};"
        : "+f"(c[0]), "+f"(c[1]), "+f"(c[2]), "+f"(c[3])
        : "r"(a[0]), "r"(a[1]), "r"(a[2]), "r"(a[3]), "r"(b[0]), "r"(b[1]));
}
__device__ __forceinline__ void split2(float x, float y, uint32_t& hi, uint32_t& lo) {
    __nv_bfloat162 h = __floats2bfloat162_rn(x, y);
    float hx = __bfloat162float(h.x), hy = __bfloat162float(h.y);
    __nv_bfloat162 l = __floats2bfloat162_rn(x - hx, y - hy);
    hi = *reinterpret_cast<uint32_t*>(&h);
    lo = *reinterpret_cast<uint32_t*>(&l);
}

// ============================================================================
// split kernels (fp32 -> bf16 hi/lo triplets)
// ============================================================================
__global__ void split_kernel(const float* __restrict__ src,
                             __nv_bfloat16* __restrict__ dst,
                             int K, int dstStride, int dstOff, int amode, int n)
{
    int i = blockIdx.x * 256 + threadIdx.x;
    if (i >= n) return;
    int r = i / K, k = i % K;
    float x = src[i];
    __nv_bfloat16 hi = __float2bfloat16(x);
    __nv_bfloat16 lo = __float2bfloat16(x - __bfloat162float(hi));
    __nv_bfloat16* d = dst + (size_t)r * dstStride + dstOff;
    d[k] = hi;
    d[K + k] = amode ? lo : hi;
    d[2 * K + k] = amode ? hi : lo;
}

__global__ void split_concat_kernel(const float* __restrict__ hid,
                                    const float* __restrict__ enc)
{
    int i = blockIdx.x * 256 + threadIdx.x;
    if (i >= S_TOT * DMODEL) return;
    int r = i / DMODEL, k = i % DMODEL;
    float x = (r < TLEN) ? enc[i] : hid[i - TLEN * DMODEL];
    __nv_bfloat16 hi = __float2bfloat16(x);
    __nv_bfloat16 lo = __float2bfloat16(x - __bfloat162float(hi));
    __nv_bfloat16* d = g_ab + (size_t)r * LDAB;
    d[k] = hi;
    d[DMODEL + k] = lo;
    d[2 * DMODEL + k] = hi;
}

// ============================================================================
// HMMA NT GEMM (unchanged from round 3)
// ============================================================================
__global__ void __launch_bounds__(256) gemm_hmma(
    const __nv_bfloat16* __restrict__ A, int lda,
    const __nv_bfloat16* __restrict__ B, int ldb,
    const float* __restrict__ bias, float* __restrict__ C, int ldc,
    int chunks, int use_atomic)
{
    __shared__ __align__(16) __nv_bfloat16 smA[2][128 * 40];
    __shared__ __align__(16) __nv_bfloat16 smB[2][128 * 40];

    const int tid = threadIdx.x;
    const int lane = tid & 31;
    const int wid = tid >> 5;
    const int wm0 = (wid & 1) * 64;
    const int wn0 = (wid >> 1) * 32;
    const int r0 = blockIdx.y << 7;
    const int c0 = blockIdx.x << 7;
    const int kbase = blockIdx.z * chunks * 32;

    float acc[4][4][4];
#pragma unroll
    for (int i = 0; i < 4; i++)
#pragma unroll
        for (int j = 0; j < 4; j++)
#pragma unroll
            for (int e = 0; e < 4; e++) acc[i][j][e] = 0.f;

    const int lrow = tid >> 2;
    const int lpart = tid & 3;
    const __nv_bfloat16* Ag = A + (size_t)(r0 + lrow) * lda + kbase + lpart * 8;
    const __nv_bfloat16* Bg = B + (size_t)(c0 + lrow) * ldb + kbase + lpart * 8;
    const size_t a64 = (size_t)64 * lda;
    const size_t b64 = (size_t)64 * ldb;

    auto load_tile = [&](int c) {
        int b = c & 1;
        uint32_t sa = s2u(&smA[b][0]) + lrow * 80 + lpart * 16;
        uint32_t sb = s2u(&smB[b][0]) + lrow * 80 + lpart * 16;
        const __nv_bfloat16* ga = Ag + c * 32;
        const __nv_bfloat16* gb = Bg + c * 32;
        cpa16(sa, ga);
        cpa16(sa + 64 * 80, ga + a64);
        cpa16(sb, gb);
        cpa16(sb + 64 * 80, gb + b64);
        cpa_commit();
    };

    load_tile(0);

    for (int c = 0; c < chunks; c++) {
        if (c + 1 < chunks) {
            load_tile(c + 1);
            asm volatile("cp.async.wait_group 1;" ::: "memory");
        } else {
            asm volatile("cp.async.wait_group 0;" ::: "memory");
        }
        __syncthreads();

        int b = c & 1;
        uint32_t saw = s2u(&smA[b][0]) + (uint32_t)((wm0 + (lane & 15)) * 80)
                       + ((lane >> 4) << 4);
        uint32_t sbw = s2u(&smB[b][0]) + (uint32_t)((wn0 + (lane & 7)) * 80)
                       + (((lane >> 3) & 1) << 4);
#pragma unroll
        for (int s = 0; s < 2; s++) {
            uint32_t af[4][4], bf[4][2];
#pragma unroll
            for (int i = 0; i < 4; i++) ldsm4(af[i], saw + i * (16 * 80) + s * 32);
#pragma unroll
            for (int j = 0; j < 4; j++) ldsm2(bf[j], sbw + j * (8 * 80) + s * 32);
#pragma unroll
            for (int i = 0; i < 4; i++)
#pragma unroll
                for (int j = 0; j < 4; j++)
                    mma_bf16(acc[i][j], af[i], bf[j]);
        }
        __syncthreads();
    }

#pragma unroll
    for (int i = 0; i < 4; i++) {
#pragma unroll
        for (int j = 0; j < 4; j++) {
            int mm = r0 + wm0 + i * 16 + (lane >> 2);
            int nn = c0 + wn0 + j * 8 + (lane & 3) * 2;
            float* p0 = C + (size_t)mm * ldc + nn;
            float* p1 = C + (size_t)(mm + 8) * ldc + nn;
            if (use_atomic) {
                atomicAdd(p0,     acc[i][j][0]);
                atomicAdd(p0 + 1, acc[i][j][1]);
                atomicAdd(p1,     acc[i][j][2]);
                atomicAdd(p1 + 1, acc[i][j][3]);
            } else {
                float b0v = bias ? bias[nn] : 0.f;
                float b1v = bias ? bias[nn + 1] : 0.f;
                p0[0] = acc[i][j][0] + b0v;
                p0[1] = acc[i][j][1] + b1v;
                p1[0] = acc[i][j][2] + b0v;
                p1[1] = acc[i][j][3] + b1v;
            }
        }
    }
}

// ============================================================================
// LN(64) + RoPE -> bf16 hi/lo planes, head-major [head][pos][64]
// ============================================================================
__global__ void ln_rope_split(const float* __restrict__ x,
                              const float* __restrict__ gamma,
                              const float* __restrict__ beta,
                              const float* __restrict__ cosb,
                              const float* __restrict__ sinb,
                              __nv_bfloat16* __restrict__ hi_out,
                              __nv_bfloat16* __restrict__ lo_out,
                              float qscale)
{
    int gw = (blockIdx.x * blockDim.x + threadIdx.x) >> 5;
    int lane = threadIdx.x & 31;
    if (gw >= S_TOT * NHEADS) return;
    int pos = gw / NHEADS, head = gw % NHEADS;
    const float* row = x + (size_t)pos * DMODEL + head * HDIM;

    float2 v = ((const float2*)row)[lane];
    float sum = v.x + v.y;
#pragma unroll
    for (int o = 16; o; o >>= 1) sum += __shfl_xor_sync(0xffffffffu, sum, o);
    float mu = sum * (1.f / 64.f);
    float dx = v.x - mu, dy = v.y - mu;
    float vs = dx * dx + dy * dy;
#pragma unroll
    for (int o = 16; o; o >>= 1) vs += __shfl_xor_sync(0xffffffffu, vs, o);
    float inv = rsqrtf(vs * (1.f / 64.f) + 1e-5f);

    float y0 = dx * inv * gamma[lane * 2]     + beta[lane * 2];
    float y1 = dy * inv * gamma[lane * 2 + 1] + beta[lane * 2 + 1];

    if (pos >= TLEN) {
        int r = pos - TLEN;
        float c0 = cosb[r * HDIM + lane * 2], c1 = cosb[r * HDIM + lane * 2 + 1];
        float s0 = sinb[r * HDIM + lane * 2], s1 = sinb[r * HDIM + lane * 2 + 1];
        float t0 = y0 * c0 - y1 * s0;
        float t1 = y1 * c1 + y0 * s1;
        y0 = t0; y1 = t1;
    }
    y0 *= qscale; y1 *= qscale;

    size_t base = ((size_t)head * S_TOT + pos) * HDIM;
    uint32_t hi, lo;
    split2(y0, y1, hi, lo);
    *reinterpret_cast<uint32_t*>(hi_out + base + lane * 2) = hi;
    *reinterpret_cast<uint32_t*>(lo_out + base + lane * 2) = lo;
}

// ============================================================================
// V transpose + split: g_v[pos][head*64+d] -> Vt planes [head][d][pos]
// grid (S_TOT/64, NHEADS), block 256
// ============================================================================
__global__ void vt_split()
{
    __shared__ float tile[64][65];
    int head = blockIdx.y, p0 = blockIdx.x * 64;
    int tid = threadIdx.x;
#pragma unroll
    for (int i = 0; i < 16; i++) {
        int idx = tid + i * 256;
        int p = idx >> 6, d = idx & 63;
        tile[p][d] = g_v[(size_t)(p0 + p) * DMODEL + head * HDIM + d];
    }
    __syncthreads();
#pragma unroll
    for (int i = 0; i < 16; i++) {
        int idx = tid + i * 256;
        int d = idx >> 6, p = idx & 63;
        float x = tile[p][d];
        __nv_bfloat16 hi = __float2bfloat16(x);
        __nv_bfloat16 lo = __float2bfloat16(x - __bfloat162float(hi));
        size_t o = ((size_t)head * HDIM + d) * S_TOT + p0 + p;
        g_vthi[o] = hi;
        g_vtlo[o] = lo;
    }
}

// ============================================================================
// HMMA flash attention: CTA = 128 queries x 1 head, 8 warps x 16 rows.
// Split-precision scores and PV. Double-buffered K/V tiles of 128 keys.
// ============================================================================
#define ATT_SQH 0
#define ATT_SQL 18432
#define ATT_SK  36864            // + buf*36864 + plane*18432
#define ATT_SV  110592           // + buf*34816 + plane*17408
#define ATT_SMEM 180224

__global__ void __launch_bounds__(256) attn_hmma()
{
    extern __shared__ char sm[];
    const int head = blockIdx.y;
    const int q0 = blockIdx.x * 128;
    const int tid = threadIdx.x;
    const int lane = tid & 31;
    const int wid = tid >> 5;

    const uint32_t smb = s2u(sm);

    // ---- load Q tile (hi/lo), group 0 ----
    {
        const __nv_bfloat16* Qh = g_qhi + ((size_t)head * S_TOT + q0) * HDIM;
        const __nv_bfloat16* Ql = g_qlo + ((size_t)head * S_TOT + q0) * HDIM;
#pragma unroll
        for (int i = 0; i < 4; i++) {
            int idx = tid + i * 256;
            int row = idx >> 3, ch = idx & 7;
            cpa16(smb + ATT_SQH + row * 144 + ch * 16, Qh + row * HDIM + ch * 8);
            cpa16(smb + ATT_SQL + row * 144 + ch * 16, Ql + row * HDIM + ch * 8);
        }
        cpa_commit();
    }

    auto load_kv = [&](int c) {
        int buf = c & 1;
        const __nv_bfloat16* Kh = g_khi + ((size_t)head * S_TOT + c * 128) * HDIM;
        const __nv_bfloat16* Kl = g_klo + ((size_t)head * S_TOT + c * 128) * HDIM;
        uint32_t kb = smb + ATT_SK + buf * 36864;
#pragma unroll
        for (int i = 0; i < 4; i++) {
            int idx = tid + i * 256;
            int row = idx >> 3, ch = idx & 7;
            cpa16(kb + row * 144 + ch * 16, Kh + row * HDIM + ch * 8);
            cpa16(kb + 18432 + row * 144 + ch * 16, Kl + row * HDIM + ch * 8);
        }
        const __nv_bfloat16* Vh = g_vthi + (size_t)head * HDIM * S_TOT + c * 128;
        const __nv_bfloat16* Vl = g_vtlo + (size_t)head * HDIM * S_TOT + c * 128;
        uint32_t vb = smb + ATT_SV + buf * 34816;
#pragma unroll
        for (int i = 0; i < 4; i++) {
            int idx = tid + i * 256;
            int d = idx >> 4, ch = idx & 15;
            cpa16(vb + d * 272 + ch * 16, Vh + (size_t)d * S_TOT + ch * 8);
            cpa16(vb + 17408 + d * 272 + ch * 16, Vl + (size_t)d * S_TOT + ch * 8);
        }
        cpa_commit();
    };

    load_kv(0);

    uint32_t aQh[4][4], aQl[4][4];
    float O[8][4];
#pragma unroll
    for (int j = 0; j < 8; j++)
#pragma unroll
        for (int e = 0; e < 4; e++) O[j][e] = 0.f;
    float m0 = -1e30f, m1 = -1e30f, l0 = 0.f, l1 = 0.f;

    for (int c = 0; c < S_TOT / 128; c++) {
        if (c + 1 < S_TOT / 128) {
            load_kv(c + 1);
            asm volatile("cp.async.wait_group 1;" ::: "memory");
        } else {
            asm volatile("cp.async.wait_group 0;" ::: "memory");
        }
        __syncthreads();

        if (c == 0) {
            uint32_t qa = smb + (uint32_t)((wid * 16 + (lane & 15)) * 144)
                          + ((lane >> 4) << 4);
#pragma unroll
            for (int kc = 0; kc < 4; kc++) {
                ldsm4(aQh[kc], qa + ATT_SQH + kc * 32);
                ldsm4(aQl[kc], qa + ATT_SQL + kc * 32);
            }
        }

        int buf = c & 1;
        // ---- scores ----
        float s[16][4];
#pragma unroll
        for (int j = 0; j < 16; j++)
#pragma unroll
            for (int e = 0; e < 4; e++) s[j][e] = 0.f;

        uint32_t kb = smb + ATT_SK + buf * 36864 + (uint32_t)((lane & 7) * 144)
                      + (((lane >> 3) & 1) << 4);
#pragma unroll
        for (int kc = 0; kc < 4; kc++) {
#pragma unroll
            for (int j = 0; j < 16; j++) {
                uint32_t bh[2], bl[2];
                uint32_t a = kb + j * (8 * 144) + kc * 32;
                ldsm2(bh, a);
                mma_bf16(s[j], aQh[kc], bh);
                mma_bf16(s[j], aQl[kc], bh);
                ldsm2(bl, a + 18432);
                mma_bf16(s[j], aQh[kc], bl);
            }
        }

        // ---- online softmax (rows r = lane>>2 and r+8 within warp tile) ----
        float mx0 = -1e30f, mx1 = -1e30f;
#pragma unroll
        for (int j = 0; j < 16; j++) {
            mx0 = fmaxf(mx0, fmaxf(s[j][0], s[j][1]));
            mx1 = fmaxf(mx1, fmaxf(s[j][2], s[j][3]));
        }
        mx0 = fmaxf(mx0, __shfl_xor_sync(0xffffffffu, mx0, 1));
        mx0 = fmaxf(mx0, __shfl_xor_sync(0xffffffffu, mx0, 2));
        mx1 = fmaxf(mx1, __shfl_xor_sync(0xffffffffu, mx1, 1));
        mx1 = fmaxf(mx1, __shfl_xor_sync(0xffffffffu, mx1, 2));
        float mn0 = fmaxf(m0, mx0), mn1 = fmaxf(m1, mx1);
        float cr0 = __expf(m0 - mn0), cr1 = __expf(m1 - mn1);
        m0 = mn0; m1 = mn1;

        float rs0 = 0.f, rs1 = 0.f;
#pragma unroll
        for (int j = 0; j < 16; j++) {
            s[j][0] = __expf(s[j][0] - mn0);
            s[j][1] = __expf(s[j][1] - mn0);
            s[j][2] = __expf(s[j][2] - mn1);
            s[j][3] = __expf(s[j][3] - mn1);
            rs0 += s[j][0] + s[j][1];
            rs1 += s[j][2] + s[j][3];
        }
        rs0 += __shfl_xor_sync(0xffffffffu, rs0, 1);
        rs0 += __shfl_xor_sync(0xffffffffu, rs0, 2);
        rs1 += __shfl_xor_sync(0xffffffffu, rs1, 1);
        rs1 += __shfl_xor_sync(0xffffffffu, rs1, 2);
        l0 = l0 * cr0 + rs0;
        l1 = l1 * cr1 + rs1;

#pragma unroll
        for (int j = 0; j < 8; j++) {
            O[j][0] *= cr0; O[j][1] *= cr0;
            O[j][2] *= cr1; O[j][3] *= cr1;
        }

        // ---- PV (split P into hi/lo fragments in registers) ----
        uint32_t vb = smb + ATT_SV + buf * 34816 + (uint32_t)((lane & 7) * 272)
                      + (((lane >> 3) & 1) << 4);
#pragma unroll
        for (int ck = 0; ck < 8; ck++) {
            uint32_t ah[4], al[4];
            split2(s[2 * ck][0],     s[2 * ck][1],     ah[0], al[0]);
            split2(s[2 * ck][2],     s[2 * ck][3],     ah[1], al[1]);
            split2(s[2 * ck + 1][0], s[2 * ck + 1][1], ah[2], al[2]);
            split2(s[2 * ck + 1][2], s[2 * ck + 1][3], ah[3], al[3]);
#pragma unroll
            for (int jd = 0; jd < 8; jd++) {
                uint32_t bh[2], bl[2];
                uint32_t a = vb + jd * (8 * 272) + ck * 32;
                ldsm2(bh, a);
                mma_bf16(O[jd], ah, bh);
                mma_bf16(O[jd], al, bh);
                ldsm2(bl, a + 17408);
                mma_bf16(O[jd], ah, bl);
            }
        }
        __syncthreads();
    }

    // ---- write out ----
    float i0 = 1.f / l0, i1 = 1.f / l1;
    int r = q0 + wid * 16 + (lane >> 2);
    int cb = head * HDIM + (lane & 3) * 2;
#pragma unroll
    for (int jd = 0; jd < 8; jd++) {
        float* p0 = g_attn + (size_t)r * DMODEL + cb + jd * 8;
        float* p1 = g_attn + (size_t)(r + 8) * DMODEL + cb + jd * 8;
        p0[0] = O[jd][0] * i0; p0[1] = O[jd][1] * i0;
        p1[0] = O[jd][2] * i1; p1[1] = O[jd][3] * i1;
    }
}

// ---------------- row permute into d_out: [hid_out | enc_out] ---------------
__global__ void permute_kernel(float* __restrict__ out) {
    int i = blockIdx.x * 256 + threadIdx.x;
    if (i >= S_TOT * DMODEL) return;
    int row = i / DMODEL;
    if (row < TLEN) out[(size_t)VLEN * DMODEL + i] = g_out[i];
    else            out[i - TLEN * DMODEL] = g_out[i];
}

// ============================================================================
extern "C" void kernel_launch(void* const* d_in, const int* in_sizes, int n_in,
                              void* d_out, int out_size)
{
    const float* hid = (const float*)d_in[0];
    const float* enc = (const float*)d_in[1];
    const float* rc  = (const float*)d_in[2];
    const float* rs  = (const float*)d_in[3];
    const float* Wq  = (const float*)d_in[4];  const float* bq = (const float*)d_in[5];
    const float* Wk  = (const float*)d_in[6];  const float* bk = (const float*)d_in[7];
    const float* Wv  = (const float*)d_in[8];  const float* bv = (const float*)d_in[9];
    const float* Wo  = (const float*)d_in[10]; const float* bo = (const float*)d_in[11];
    const float* lqd = (const float*)d_in[12]; const float* lqu = (const float*)d_in[13];
    const float* lkd = (const float*)d_in[14]; const float* lku = (const float*)d_in[15];
    const float* lvd = (const float*)d_in[16]; const float* lvu = (const float*)d_in[17];
    const float* lpd = (const float*)d_in[18]; const float* lpu = (const float*)d_in[19];
    const float* gq  = (const float*)d_in[20]; const float* btq = (const float*)d_in[21];
    const float* gk  = (const float*)d_in[22]; const float* btk = (const float*)d_in[23];

    static int attr_done = 0;
    if (!attr_done) {
        cudaFuncSetAttribute(attn_hmma, cudaFuncAttributeMaxDynamicSharedMemorySize,
                             ATT_SMEM);
        attr_done = 1;
    }

    float *pq, *pk, *pv, *pt, *pa, *po;
    __nv_bfloat16 *pab, *pwb, *pldb, *pqh, *pql, *pkh, *pkl;
    cudaGetSymbolAddress((void**)&pq, g_q);
    cudaGetSymbolAddress((void**)&pk, g_k);
    cudaGetSymbolAddress((void**)&pv, g_v);
    cudaGetSymbolAddress((void**)&pt, g_t);
    cudaGetSymbolAddress((void**)&pa, g_attn);
    cudaGetSymbolAddress((void**)&po, g_out);
    cudaGetSymbolAddress((void**)&pab, g_ab);
    cudaGetSymbolAddress((void**)&pwb, g_wb);
    cudaGetSymbolAddress((void**)&pldb, g_ldb);
    cudaGetSymbolAddress((void**)&pqh, g_qhi);
    cudaGetSymbolAddress((void**)&pql, g_qlo);
    cudaGetSymbolAddress((void**)&pkh, g_khi);
    cudaGetSymbolAddress((void**)&pkl, g_klo);

    const int nHD = S_TOT * DMODEL;
    const int nW  = DMODEL * DMODEL;
    const int nLD = RANK_ * DMODEL;
    const int nLU = DMODEL * RANK_;
    const int nT  = S_TOT * RANK_;

    dim3 big_grid(DMODEL / 128, S_TOT / 128, 1);
    dim3 lora_grid(1, S_TOT / 128, 8);
    const int BIG_CH = LDAB / 32;
    const int LORA_CH = (K3 / 32) / 8;

    split_concat_kernel<<<(nHD + 255) / 256, 256>>>(hid, enc);

    struct Proj { const float* W; const float* b; const float* ld; const float* lu; float* out; };
    Proj projs[3] = { {Wq, bq, lqd, lqu, pq}, {Wk, bk, lkd, lku, pk}, {Wv, bv, lvd, lvu, pv} };

    for (int p = 0; p < 3; p++) {
        split_kernel<<<(nW + 255) / 256, 256>>>(projs[p].W, pwb, DMODEL, LDAB, 0, 0, nW);
        split_kernel<<<(nLU + 255) / 256, 256>>>(projs[p].lu, pwb, RANK_, LDAB, K3, 0, nLU);
        split_kernel<<<(nLD + 255) / 256, 256>>>(projs[p].ld, pldb, DMODEL, K3, 0, 0, nLD);
        cudaMemsetAsync(pt, 0, nT * sizeof(float));
        gemm_hmma<<<lora_grid, 256>>>(pab, LDAB, pldb, K3, nullptr, pt, RANK_, LORA_CH, 1);
        split_kernel<<<(nT + 255) / 256, 256>>>(pt, pab, RANK_, LDAB, K3, 1, nT);
        gemm_hmma<<<big_grid, 256>>>(pab, LDAB, pwb, LDAB, projs[p].b, projs[p].out,
                                     DMODEL, BIG_CH, 0);
    }

    // LN + RoPE -> split planes (Q pre-scaled by 1/sqrt(64))
    int ln_blocks = (S_TOT * NHEADS * 32 + 255) / 256;
    ln_rope_split<<<ln_blocks, 256>>>(pq, gq, btq, rc, rs, pqh, pql, 0.125f);
    ln_rope_split<<<ln_blocks, 256>>>(pk, gk, btk, rc, rs, pkh, pkl, 1.0f);
    vt_split<<<dim3(S_TOT / 64, NHEADS), 256>>>();

    // HMMA flash attention
    attn_hmma<<<dim3(S_TOT / 128, NHEADS), 256, ATT_SMEM>>>();

    // output projection
    split_kernel<<<(nHD + 255) / 256, 256>>>(pa, pab, DMODEL, LDAB, 0, 1, nHD);
    split_kernel<<<(nW + 255) / 256, 256>>>(Wo, pwb, DMODEL, LDAB, 0, 0, nW);
    split_kernel<<<(nLU + 255) / 256, 256>>>(lpu, pwb, RANK_, LDAB, K3, 0, nLU);
    split_kernel<<<(nLD + 255) / 256, 256>>>(lpd, pldb, DMODEL, K3, 0, 0, nLD);
    cudaMemsetAsync(pt, 0, nT * sizeof(float));
    gemm_hmma<<<lora_grid, 256>>>(pab, LDAB, pldb, K3, nullptr, pt, RANK_, LORA_CH, 1);
    split_kernel<<<(nT + 255) / 256, 256>>>(pt, pab, RANK_, LDAB, K3, 1, nT);
    gemm_hmma<<<big_grid, 256>>>(pab, LDAB, pwb, LDAB, bo, po, DMODEL, BIG_CH, 0);

    permute_kernel<<<(nHD + 255) / 256, 256>>>((float*)d_out);
}

// round 5
// speedup vs baseline: 4.1668x; 1.3308x over previous
#include <cuda_runtime.h>
#include <cuda_bf16.h>
#include <cuda_fp16.h>
#include <cstdint>

#define S_TOT 2048
#define DMODEL 3072
#define NHEADS 48
#define HDIM 64
#define RANK_ 128
#define TLEN 226
#define VLEN 1822

#define K2 (2 * DMODEL)       // 6144: fp16 2-term width of D
#define KR2 (2 * RANK_)       // 256
#define LDAB (K2 + KR2)       // 6400: fused A / W operand width

// ---------------- fp32 scratch ----------------------------------------------
__device__ __align__(256) float g_q[S_TOT * DMODEL];
__device__ __align__(256) float g_k[S_TOT * DMODEL];
__device__ __align__(256) float g_v[S_TOT * DMODEL];
__device__ __align__(256) float g_t[S_TOT * RANK_];
__device__ __align__(256) float g_attn[S_TOT * DMODEL];
__device__ __align__(256) float g_out[S_TOT * DMODEL];

// ---------------- fp16 split operand buffers (linear layers) -----------------
__device__ __align__(256) __half g_ab[(size_t)S_TOT * LDAB];
__device__ __align__(256) __half g_wb[(size_t)DMODEL * LDAB];
__device__ __align__(256) __half g_ldb[(size_t)RANK_ * K2];

// ---------------- attention split planes (bf16 3-term, head-major) ----------
__device__ __align__(256) __nv_bfloat16 g_qhi[(size_t)NHEADS * S_TOT * HDIM];
__device__ __align__(256) __nv_bfloat16 g_qlo[(size_t)NHEADS * S_TOT * HDIM];
__device__ __align__(256) __nv_bfloat16 g_khi[(size_t)NHEADS * S_TOT * HDIM];
__device__ __align__(256) __nv_bfloat16 g_klo[(size_t)NHEADS * S_TOT * HDIM];
__device__ __align__(256) __nv_bfloat16 g_vthi[(size_t)NHEADS * HDIM * S_TOT];
__device__ __align__(256) __nv_bfloat16 g_vtlo[(size_t)NHEADS * HDIM * S_TOT];

// ============================================================================
// helpers
// ============================================================================
__device__ __forceinline__ uint32_t s2u(const void* p) {
    return (uint32_t)__cvta_generic_to_shared(p);
}
__device__ __forceinline__ void cpa16(uint32_t s, const void* g) {
    asm volatile("cp.async.cg.shared.global [%0], [%1], 16;" :: "r"(s), "l"(g));
}
__device__ __forceinline__ void cpa_commit() {
    asm volatile("cp.async.commit_group;" ::: "memory");
}
__device__ __forceinline__ void ldsm4(uint32_t* r, uint32_t a) {
    asm volatile("ldmatrix.sync.aligned.m8n8.x4.shared.b16 {%0,%1,%2,%3}, [%4];"
                 : "=r"(r[0]), "=r"(r[1]), "=r"(r[2]), "=r"(r[3]) : "r"(a));
}
__device__ __forceinline__ void ldsm2(uint32_t* r, uint32_t a) {
    asm volatile("ldmatrix.sync.aligned.m8n8.x2.shared.b16 {%0,%1}, [%2];"
                 : "=r"(r[0]), "=r"(r[1]) : "r"(a));
}
__device__ __forceinline__ void mma_bf16(float* c, const uint32_t* a, const uint32_t* b) {
    asm volatile(
        "mma.sync.aligned.m16n8k16.row.col.f32.bf16.bf16.f32 "
        "{%0,%1,%2,%3}, {%4,%5,%6,%7}, {%8,%9}, {%0,%1,%2,%3};"
        : "+f"(c[0]), "+f"(c[1]), "+f"(c[2]), "+f"(c[3])
        : "r"(a[0]), "r"(a[1]), "r"(a[2]), "r"(a[3]), "r"(b[0]), "r"(b[1]));
}
__device__ __forceinline__ void mma_f16(float* c, const uint32_t* a, const uint32_t* b) {
    asm volatile(
        "mma.sync.aligned.m16n8k16.row.col.f32.f16.f16.f32 "
        "{%0,%1,%2,%3}, {%4,%5,%6,%7}, {%8,%9}, {%0,%1,%2,%3};"
        : "+f"(c[0]), "+f"(c[1]), "+f"(c[2]), "+f"(c[3])
        : "r"(a[0]), "r"(a[1]), "r"(a[2]), "r"(a[3]), "r"(b[0]), "r"(b[1]));
}
__device__ __forceinline__ void split2bf(float x, float y, uint32_t& hi, uint32_t& lo) {
    __nv_bfloat162 h = __floats2bfloat162_rn(x, y);
    float hx = __bfloat162float(h.x), hy = __bfloat162float(h.y);
    __nv_bfloat162 l = __floats2bfloat162_rn(x - hx, y - hy);
    hi = *reinterpret_cast<uint32_t*>(&h);
    lo = *reinterpret_cast<uint32_t*>(&l);
}

// ============================================================================
// fp16 split kernels: amode=1 -> [hi, lo] (A side), amode=0 -> [hi, hi] (B side)
// ============================================================================
__global__ void split_kernel_h(const float* __restrict__ src,
                               __half* __restrict__ dst,
                               int K, int dstStride, int dstOff, int amode, int n)
{
    int i = blockIdx.x * 256 + threadIdx.x;
    if (i >= n) return;
    int r = i / K, k = i % K;
    float x = src[i];
    __half hi = __float2half_rn(x);
    __half sec = amode ? __float2half_rn(x - __half2float(hi)) : hi;
    __half* d = dst + (size_t)r * dstStride + dstOff;
    d[k] = hi;
    d[K + k] = sec;
}

// fused concat(enc,hid) + A-split into g_ab cols [0, K2)
__global__ void split_concat_kernel(const float* __restrict__ hid,
                                    const float* __restrict__ enc)
{
    int i = blockIdx.x * 256 + threadIdx.x;
    if (i >= S_TOT * DMODEL) return;
    int r = i / DMODEL, k = i % DMODEL;
    float x = (r < TLEN) ? enc[i] : hid[i - TLEN * DMODEL];
    __half hi = __float2half_rn(x);
    __half lo = __float2half_rn(x - __half2float(hi));
    __half* d = g_ab + (size_t)r * LDAB;
    d[k] = hi;
    d[DMODEL + k] = lo;
}

// ============================================================================
// HMMA NT GEMM (fp16 operands, fp32 accum) — structure as round 3/4
// ============================================================================
__global__ void __launch_bounds__(256) gemm_hmma(
    const __half* __restrict__ A, int lda,
    const __half* __restrict__ B, int ldb,
    const float* __restrict__ bias, float* __restrict__ C, int ldc,
    int chunks, int use_atomic)
{
    __shared__ __align__(16) __half smA[2][128 * 40];
    __shared__ __align__(16) __half smB[2][128 * 40];

    const int tid = threadIdx.x;
    const int lane = tid & 31;
    const int wid = tid >> 5;
    const int wm0 = (wid & 1) * 64;
    const int wn0 = (wid >> 1) * 32;
    const int r0 = blockIdx.y << 7;
    const int c0 = blockIdx.x << 7;
    const int kbase = blockIdx.z * chunks * 32;

    float acc[4][4][4];
#pragma unroll
    for (int i = 0; i < 4; i++)
#pragma unroll
        for (int j = 0; j < 4; j++)
#pragma unroll
            for (int e = 0; e < 4; e++) acc[i][j][e] = 0.f;

    const int lrow = tid >> 2;
    const int lpart = tid & 3;
    const __half* Ag = A + (size_t)(r0 + lrow) * lda + kbase + lpart * 8;
    const __half* Bg = B + (size_t)(c0 + lrow) * ldb + kbase + lpart * 8;
    const size_t a64 = (size_t)64 * lda;
    const size_t b64 = (size_t)64 * ldb;

    auto load_tile = [&](int c) {
        int b = c & 1;
        uint32_t sa = s2u(&smA[b][0]) + lrow * 80 + lpart * 16;
        uint32_t sb = s2u(&smB[b][0]) + lrow * 80 + lpart * 16;
        const __half* ga = Ag + c * 32;
        const __half* gb = Bg + c * 32;
        cpa16(sa, ga);
        cpa16(sa + 64 * 80, ga + a64);
        cpa16(sb, gb);
        cpa16(sb + 64 * 80, gb + b64);
        cpa_commit();
    };

    load_tile(0);

    for (int c = 0; c < chunks; c++) {
        if (c + 1 < chunks) {
            load_tile(c + 1);
            asm volatile("cp.async.wait_group 1;" ::: "memory");
        } else {
            asm volatile("cp.async.wait_group 0;" ::: "memory");
        }
        __syncthreads();

        int b = c & 1;
        uint32_t saw = s2u(&smA[b][0]) + (uint32_t)((wm0 + (lane & 15)) * 80)
                       + ((lane >> 4) << 4);
        uint32_t sbw = s2u(&smB[b][0]) + (uint32_t)((wn0 + (lane & 7)) * 80)
                       + (((lane >> 3) & 1) << 4);
#pragma unroll
        for (int s = 0; s < 2; s++) {
            uint32_t af[4][4], bf[4][2];
#pragma unroll
            for (int i = 0; i < 4; i++) ldsm4(af[i], saw + i * (16 * 80) + s * 32);
#pragma unroll
            for (int j = 0; j < 4; j++) ldsm2(bf[j], sbw + j * (8 * 80) + s * 32);
#pragma unroll
            for (int i = 0; i < 4; i++)
#pragma unroll
                for (int j = 0; j < 4; j++)
                    mma_f16(acc[i][j], af[i], bf[j]);
        }
        __syncthreads();
    }

#pragma unroll
    for (int i = 0; i < 4; i++) {
#pragma unroll
        for (int j = 0; j < 4; j++) {
            int mm = r0 + wm0 + i * 16 + (lane >> 2);
            int nn = c0 + wn0 + j * 8 + (lane & 3) * 2;
            float* p0 = C + (size_t)mm * ldc + nn;
            float* p1 = C + (size_t)(mm + 8) * ldc + nn;
            if (use_atomic) {
                atomicAdd(p0,     acc[i][j][0]);
                atomicAdd(p0 + 1, acc[i][j][1]);
                atomicAdd(p1,     acc[i][j][2]);
                atomicAdd(p1 + 1, acc[i][j][3]);
            } else {
                float b0v = bias ? bias[nn] : 0.f;
                float b1v = bias ? bias[nn + 1] : 0.f;
                p0[0] = acc[i][j][0] + b0v;
                p0[1] = acc[i][j][1] + b1v;
                p1[0] = acc[i][j][2] + b0v;
                p1[1] = acc[i][j][3] + b1v;
            }
        }
    }
}

// ============================================================================
// LN(64) + RoPE -> bf16 hi/lo planes, head-major [head][pos][64]
// ============================================================================
__global__ void ln_rope_split(const float* __restrict__ x,
                              const float* __restrict__ gamma,
                              const float* __restrict__ beta,
                              const float* __restrict__ cosb,
                              const float* __restrict__ sinb,
                              __nv_bfloat16* __restrict__ hi_out,
                              __nv_bfloat16* __restrict__ lo_out,
                              float qscale)
{
    int gw = (blockIdx.x * blockDim.x + threadIdx.x) >> 5;
    int lane = threadIdx.x & 31;
    if (gw >= S_TOT * NHEADS) return;
    int pos = gw / NHEADS, head = gw % NHEADS;
    const float* row = x + (size_t)pos * DMODEL + head * HDIM;

    float2 v = ((const float2*)row)[lane];
    float sum = v.x + v.y;
#pragma unroll
    for (int o = 16; o; o >>= 1) sum += __shfl_xor_sync(0xffffffffu, sum, o);
    float mu = sum * (1.f / 64.f);
    float dx = v.x - mu, dy = v.y - mu;
    float vs = dx * dx + dy * dy;
#pragma unroll
    for (int o = 16; o; o >>= 1) vs += __shfl_xor_sync(0xffffffffu, vs, o);
    float inv = rsqrtf(vs * (1.f / 64.f) + 1e-5f);

    float y0 = dx * inv * gamma[lane * 2]     + beta[lane * 2];
    float y1 = dy * inv * gamma[lane * 2 + 1] + beta[lane * 2 + 1];

    if (pos >= TLEN) {
        int r = pos - TLEN;
        float c0 = cosb[r * HDIM + lane * 2], c1 = cosb[r * HDIM + lane * 2 + 1];
        float s0 = sinb[r * HDIM + lane * 2], s1 = sinb[r * HDIM + lane * 2 + 1];
        float t0 = y0 * c0 - y1 * s0;
        float t1 = y1 * c1 + y0 * s1;
        y0 = t0; y1 = t1;
    }
    y0 *= qscale; y1 *= qscale;

    size_t base = ((size_t)head * S_TOT + pos) * HDIM;
    uint32_t hi, lo;
    split2bf(y0, y1, hi, lo);
    *reinterpret_cast<uint32_t*>(hi_out + base + lane * 2) = hi;
    *reinterpret_cast<uint32_t*>(lo_out + base + lane * 2) = lo;
}

// ============================================================================
// V transpose + split (bf16)
// ============================================================================
__global__ void vt_split()
{
    __shared__ float tile[64][65];
    int head = blockIdx.y, p0 = blockIdx.x * 64;
    int tid = threadIdx.x;
#pragma unroll
    for (int i = 0; i < 16; i++) {
        int idx = tid + i * 256;
        int p = idx >> 6, d = idx & 63;
        tile[p][d] = g_v[(size_t)(p0 + p) * DMODEL + head * HDIM + d];
    }
    __syncthreads();
#pragma unroll
    for (int i = 0; i < 16; i++) {
        int idx = tid + i * 256;
        int d = idx >> 6, p = idx & 63;
        float x = tile[p][d];
        __nv_bfloat16 hi = __float2bfloat16(x);
        __nv_bfloat16 lo = __float2bfloat16(x - __bfloat162float(hi));
        size_t o = ((size_t)head * HDIM + d) * S_TOT + p0 + p;
        g_vthi[o] = hi;
        g_vtlo[o] = lo;
    }
}

// ============================================================================
// HMMA flash attention (bf16 3-term, unchanged from round 4)
// ============================================================================
#define ATT_SQH 0
#define ATT_SQL 18432
#define ATT_SK  36864
#define ATT_SV  110592
#define ATT_SMEM 180224

__global__ void __launch_bounds__(256) attn_hmma()
{
    extern __shared__ char sm[];
    const int head = blockIdx.y;
    const int q0 = blockIdx.x * 128;
    const int tid = threadIdx.x;
    const int lane = tid & 31;
    const int wid = tid >> 5;

    const uint32_t smb = s2u(sm);

    {
        const __nv_bfloat16* Qh = g_qhi + ((size_t)head * S_TOT + q0) * HDIM;
        const __nv_bfloat16* Ql = g_qlo + ((size_t)head * S_TOT + q0) * HDIM;
#pragma unroll
        for (int i = 0; i < 4; i++) {
            int idx = tid + i * 256;
            int row = idx >> 3, ch = idx & 7;
            cpa16(smb + ATT_SQH + row * 144 + ch * 16, Qh + row * HDIM + ch * 8);
            cpa16(smb + ATT_SQL + row * 144 + ch * 16, Ql + row * HDIM + ch * 8);
        }
        cpa_commit();
    }

    auto load_kv = [&](int c) {
        int buf = c & 1;
        const __nv_bfloat16* Kh = g_khi + ((size_t)head * S_TOT + c * 128) * HDIM;
        const __nv_bfloat16* Kl = g_klo + ((size_t)head * S_TOT + c * 128) * HDIM;
        uint32_t kb = smb + ATT_SK + buf * 36864;
#pragma unroll
        for (int i = 0; i < 4; i++) {
            int idx = tid + i * 256;
            int row = idx >> 3, ch = idx & 7;
            cpa16(kb + row * 144 + ch * 16, Kh + row * HDIM + ch * 8);
            cpa16(kb + 18432 + row * 144 + ch * 16, Kl + row * HDIM + ch * 8);
        }
        const __nv_bfloat16* Vh = g_vthi + (size_t)head * HDIM * S_TOT + c * 128;
        const __nv_bfloat16* Vl = g_vtlo + (size_t)head * HDIM * S_TOT + c * 128;
        uint32_t vb = smb + ATT_SV + buf * 34816;
#pragma unroll
        for (int i = 0; i < 4; i++) {
            int idx = tid + i * 256;
            int d = idx >> 4, ch = idx & 15;
            cpa16(vb + d * 272 + ch * 16, Vh + (size_t)d * S_TOT + ch * 8);
            cpa16(vb + 17408 + d * 272 + ch * 16, Vl + (size_t)d * S_TOT + ch * 8);
        }
        cpa_commit();
    };

    load_kv(0);

    uint32_t aQh[4][4], aQl[4][4];
    float O[8][4];
#pragma unroll
    for (int j = 0; j < 8; j++)
#pragma unroll
        for (int e = 0; e < 4; e++) O[j][e] = 0.f;
    float m0 = -1e30f, m1 = -1e30f, l0 = 0.f, l1 = 0.f;

    for (int c = 0; c < S_TOT / 128; c++) {
        if (c + 1 < S_TOT / 128) {
            load_kv(c + 1);
            asm volatile("cp.async.wait_group 1;" ::: "memory");
        } else {
            asm volatile("cp.async.wait_group 0;" ::: "memory");
        }
        __syncthreads();

        if (c == 0) {
            uint32_t qa = smb + (uint32_t)((wid * 16 + (lane & 15)) * 144)
                          + ((lane >> 4) << 4);
#pragma unroll
            for (int kc = 0; kc < 4; kc++) {
                ldsm4(aQh[kc], qa + ATT_SQH + kc * 32);
                ldsm4(aQl[kc], qa + ATT_SQL + kc * 32);
            }
        }

        int buf = c & 1;
        float s[16][4];
#pragma unroll
        for (int j = 0; j < 16; j++)
#pragma unroll
            for (int e = 0; e < 4; e++) s[j][e] = 0.f;

        uint32_t kb = smb + ATT_SK + buf * 36864 + (uint32_t)((lane & 7) * 144)
                      + (((lane >> 3) & 1) << 4);
#pragma unroll
        for (int kc = 0; kc < 4; kc++) {
#pragma unroll
            for (int j = 0; j < 16; j++) {
                uint32_t bh[2], bl[2];
                uint32_t a = kb + j * (8 * 144) + kc * 32;
                ldsm2(bh, a);
                mma_bf16(s[j], aQh[kc], bh);
                mma_bf16(s[j], aQl[kc], bh);
                ldsm2(bl, a + 18432);
                mma_bf16(s[j], aQh[kc], bl);
            }
        }

        float mx0 = -1e30f, mx1 = -1e30f;
#pragma unroll
        for (int j = 0; j < 16; j++) {
            mx0 = fmaxf(mx0, fmaxf(s[j][0], s[j][1]));
            mx1 = fmaxf(mx1, fmaxf(s[j][2], s[j][3]));
        }
        mx0 = fmaxf(mx0, __shfl_xor_sync(0xffffffffu, mx0, 1));
        mx0 = fmaxf(mx0, __shfl_xor_sync(0xffffffffu, mx0, 2));
        mx1 = fmaxf(mx1, __shfl_xor_sync(0xffffffffu, mx1, 1));
        mx1 = fmaxf(mx1, __shfl_xor_sync(0xffffffffu, mx1, 2));
        float mn0 = fmaxf(m0, mx0), mn1 = fmaxf(m1, mx1);
        float cr0 = __expf(m0 - mn0), cr1 = __expf(m1 - mn1);
        m0 = mn0; m1 = mn1;

        float rs0 = 0.f, rs1 = 0.f;
#pragma unroll
        for (int j = 0; j < 16; j++) {
            s[j][0] = __expf(s[j][0] - mn0);
            s[j][1] = __expf(s[j][1] - mn0);
            s[j][2] = __expf(s[j][2] - mn1);
            s[j][3] = __expf(s[j][3] - mn1);
            rs0 += s[j][0] + s[j][1];
            rs1 += s[j][2] + s[j][3];
        }
        rs0 += __shfl_xor_sync(0xffffffffu, rs0, 1);
        rs0 += __shfl_xor_sync(0xffffffffu, rs0, 2);
        rs1 += __shfl_xor_sync(0xffffffffu, rs1, 1);
        rs1 += __shfl_xor_sync(0xffffffffu, rs1, 2);
        l0 = l0 * cr0 + rs0;
        l1 = l1 * cr1 + rs1;

#pragma unroll
        for (int j = 0; j < 8; j++) {
            O[j][0] *= cr0; O[j][1] *= cr0;
            O[j][2] *= cr1; O[j][3] *= cr1;
        }

        uint32_t vb = smb + ATT_SV + buf * 34816 + (uint32_t)((lane & 7) * 272)
                      + (((lane >> 3) & 1) << 4);
#pragma unroll
        for (int ck = 0; ck < 8; ck++) {
            uint32_t ah[4], al[4];
            split2bf(s[2 * ck][0],     s[2 * ck][1],     ah[0], al[0]);
            split2bf(s[2 * ck][2],     s[2 * ck][3],     ah[1], al[1]);
            split2bf(s[2 * ck + 1][0], s[2 * ck + 1][1], ah[2], al[2]);
            split2bf(s[2 * ck + 1][2], s[2 * ck + 1][3], ah[3], al[3]);
#pragma unroll
            for (int jd = 0; jd < 8; jd++) {
                uint32_t bh[2], bl[2];
                uint32_t a = vb + jd * (8 * 272) + ck * 32;
                ldsm2(bh, a);
                mma_bf16(O[jd], ah, bh);
                mma_bf16(O[jd], al, bh);
                ldsm2(bl, a + 17408);
                mma_bf16(O[jd], ah, bl);
            }
        }
        __syncthreads();
    }

    float i0 = 1.f / l0, i1 = 1.f / l1;
    int r = q0 + wid * 16 + (lane >> 2);
    int cb = head * HDIM + (lane & 3) * 2;
#pragma unroll
    for (int jd = 0; jd < 8; jd++) {
        float* p0 = g_attn + (size_t)r * DMODEL + cb + jd * 8;
        float* p1 = g_attn + (size_t)(r + 8) * DMODEL + cb + jd * 8;
        p0[0] = O[jd][0] * i0; p0[1] = O[jd][1] * i0;
        p1[0] = O[jd][2] * i1; p1[1] = O[jd][3] * i1;
    }
}

// ---------------- row permute into d_out: [hid_out | enc_out] ---------------
__global__ void permute_kernel(float* __restrict__ out) {
    int i = blockIdx.x * 256 + threadIdx.x;
    if (i >= S_TOT * DMODEL) return;
    int row = i / DMODEL;
    if (row < TLEN) out[(size_t)VLEN * DMODEL + i] = g_out[i];
    else            out[i - TLEN * DMODEL] = g_out[i];
}

// ============================================================================
extern "C" void kernel_launch(void* const* d_in, const int* in_sizes, int n_in,
                              void* d_out, int out_size)
{
    const float* hid = (const float*)d_in[0];
    const float* enc = (const float*)d_in[1];
    const float* rc  = (const float*)d_in[2];
    const float* rs  = (const float*)d_in[3];
    const float* Wq  = (const float*)d_in[4];  const float* bq = (const float*)d_in[5];
    const float* Wk  = (const float*)d_in[6];  const float* bk = (const float*)d_in[7];
    const float* Wv  = (const float*)d_in[8];  const float* bv = (const float*)d_in[9];
    const float* Wo  = (const float*)d_in[10]; const float* bo = (const float*)d_in[11];
    const float* lqd = (const float*)d_in[12]; const float* lqu = (const float*)d_in[13];
    const float* lkd = (const float*)d_in[14]; const float* lku = (const float*)d_in[15];
    const float* lvd = (const float*)d_in[16]; const float* lvu = (const float*)d_in[17];
    const float* lpd = (const float*)d_in[18]; const float* lpu = (const float*)d_in[19];
    const float* gq  = (const float*)d_in[20]; const float* btq = (const float*)d_in[21];
    const float* gk  = (const float*)d_in[22]; const float* btk = (const float*)d_in[23];

    static int attr_done = 0;
    if (!attr_done) {
        cudaFuncSetAttribute(attn_hmma, cudaFuncAttributeMaxDynamicSharedMemorySize,
                             ATT_SMEM);
        attr_done = 1;
    }

    float *pq, *pk, *pv, *pt, *pa, *po;
    __half *pab, *pwb, *pldb;
    __nv_bfloat16 *pqh, *pql, *pkh, *pkl;
    cudaGetSymbolAddress((void**)&pq, g_q);
    cudaGetSymbolAddress((void**)&pk, g_k);
    cudaGetSymbolAddress((void**)&pv, g_v);
    cudaGetSymbolAddress((void**)&pt, g_t);
    cudaGetSymbolAddress((void**)&pa, g_attn);
    cudaGetSymbolAddress((void**)&po, g_out);
    cudaGetSymbolAddress((void**)&pab, g_ab);
    cudaGetSymbolAddress((void**)&pwb, g_wb);
    cudaGetSymbolAddress((void**)&pldb, g_ldb);
    cudaGetSymbolAddress((void**)&pqh, g_qhi);
    cudaGetSymbolAddress((void**)&pql, g_qlo);
    cudaGetSymbolAddress((void**)&pkh, g_khi);
    cudaGetSymbolAddress((void**)&pkl, g_klo);

    const int nHD = S_TOT * DMODEL;
    const int nW  = DMODEL * DMODEL;
    const int nLD = RANK_ * DMODEL;
    const int nLU = DMODEL * RANK_;
    const int nT  = S_TOT * RANK_;

    dim3 big_grid(DMODEL / 128, S_TOT / 128, 1);   // 24 x 16
    dim3 lora_grid(1, S_TOT / 128, 8);             // split-K = 8
    const int BIG_CH = LDAB / 32;                  // 200
    const int LORA_CH = (K2 / 32) / 8;             // 24

    split_concat_kernel<<<(nHD + 255) / 256, 256>>>(hid, enc);

    struct Proj { const float* W; const float* b; const float* ld; const float* lu; float* out; };
    Proj projs[3] = { {Wq, bq, lqd, lqu, pq}, {Wk, bk, lkd, lku, pk}, {Wv, bv, lvd, lvu, pv} };

    for (int p = 0; p < 3; p++) {
        split_kernel_h<<<(nW + 255) / 256, 256>>>(projs[p].W, pwb, DMODEL, LDAB, 0, 0, nW);
        split_kernel_h<<<(nLU + 255) / 256, 256>>>(projs[p].lu, pwb, RANK_, LDAB, K2, 0, nLU);
        split_kernel_h<<<(nLD + 255) / 256, 256>>>(projs[p].ld, pldb, DMODEL, K2, 0, 0, nLD);
        cudaMemsetAsync(pt, 0, nT * sizeof(float));
        gemm_hmma<<<lora_grid, 256>>>(pab, LDAB, pldb, K2, nullptr, pt, RANK_, LORA_CH, 1);
        split_kernel_h<<<(nT + 255) / 256, 256>>>(pt, pab, RANK_, LDAB, K2, 1, nT);
        gemm_hmma<<<big_grid, 256>>>(pab, LDAB, pwb, LDAB, projs[p].b, projs[p].out,
                                     DMODEL, BIG_CH, 0);
    }

    // LN + RoPE -> bf16 split planes (Q pre-scaled by 1/sqrt(64))
    int ln_blocks = (S_TOT * NHEADS * 32 + 255) / 256;
    ln_rope_split<<<ln_blocks, 256>>>(pq, gq, btq, rc, rs, pqh, pql, 0.125f);
    ln_rope_split<<<ln_blocks, 256>>>(pk, gk, btk, rc, rs, pkh, pkl, 1.0f);
    vt_split<<<dim3(S_TOT / 64, NHEADS), 256>>>();

    attn_hmma<<<dim3(S_TOT / 128, NHEADS), 256, ATT_SMEM>>>();

    // output projection
    split_kernel_h<<<(nHD + 255) / 256, 256>>>(pa, pab, DMODEL, LDAB, 0, 1, nHD);
    split_kernel_h<<<(nW + 255) / 256, 256>>>(Wo, pwb, DMODEL, LDAB, 0, 0, nW);
    split_kernel_h<<<(nLU + 255) / 256, 256>>>(lpu, pwb, RANK_, LDAB, K2, 0, nLU);
    split_kernel_h<<<(nLD + 255) / 256, 256>>>(lpd, pldb, DMODEL, K2, 0, 0, nLD);
    cudaMemsetAsync(pt, 0, nT * sizeof(float));
    gemm_hmma<<<lora_grid, 256>>>(pab, LDAB, pldb, K2, nullptr, pt, RANK_, LORA_CH, 1);
    split_kernel_h<<<(nT + 255) / 256, 256>>>(pt, pab, RANK_, LDAB, K2, 1, nT);
    gemm_hmma<<<big_grid, 256>>>(pab, LDAB, pwb, LDAB, bo, po, DMODEL, BIG_CH, 0);

    permute_kernel<<<(nHD + 255) / 256, 256>>>((float*)d_out);
}

// round 7
// speedup vs baseline: 4.9757x; 1.1941x over previous
#include <cuda_runtime.h>
#include <cuda_bf16.h>
#include <cuda_fp16.h>
#include <cstdint>

#define S_TOT 2048
#define DMODEL 3072
#define NHEADS 48
#define HDIM 64
#define RANK_ 128
#define TLEN 226
#define VLEN 1822

#define K2 (2 * DMODEL)       // 6144 fp16 2-term width of D
#define LDB_BIG (K2 + 256)    // 6400: [W-split | lu-split]
#define BIG_CHUNKS (LDB_BIG / 64)   // 100
#define H_CHUNKS (K2 / 64)          // 96

// ---------------- fp32 scratch ----------------------------------------------
__device__ __align__(256) float g_q[S_TOT * DMODEL];
__device__ __align__(256) float g_k[S_TOT * DMODEL];
__device__ __align__(256) float g_v[S_TOT * DMODEL];
__device__ __align__(256) float g_t[S_TOT * 3 * RANK_];   // stacked t (q,k,v) or out-proj t
__device__ __align__(256) float g_attn[S_TOT * DMODEL];

// ---------------- fp16 split operand buffers ---------------------------------
__device__ __align__(256) __half g_ab[(size_t)S_TOT * K2];        // A main part [hi|lo]
__device__ __align__(256) __half g_tb[(size_t)S_TOT * 768];       // A tail: per-proj [hi|lo] blocks of 256
__device__ __align__(256) __half g_wb[3][(size_t)DMODEL * LDB_BIG]; // per-proj [W|lu] splits
__device__ __align__(256) __half g_ldb[(size_t)(3 * RANK_) * K2]; // stacked lora-down split

// ---------------- attention split planes (bf16 3-term, head-major) ----------
__device__ __align__(256) __nv_bfloat16 g_qhi[(size_t)NHEADS * S_TOT * HDIM];
__device__ __align__(256) __nv_bfloat16 g_qlo[(size_t)NHEADS * S_TOT * HDIM];
__device__ __align__(256) __nv_bfloat16 g_khi[(size_t)NHEADS * S_TOT * HDIM];
__device__ __align__(256) __nv_bfloat16 g_klo[(size_t)NHEADS * S_TOT * HDIM];
__device__ __align__(256) __nv_bfloat16 g_vthi[(size_t)NHEADS * HDIM * S_TOT];
__device__ __align__(256) __nv_bfloat16 g_vtlo[(size_t)NHEADS * HDIM * S_TOT];

// ============================================================================
// helpers
// ============================================================================
__device__ __forceinline__ uint32_t s2u(const void* p) {
    return (uint32_t)__cvta_generic_to_shared(p);
}
__device__ __forceinline__ void cpa16(uint32_t s, const void* g) {
    asm volatile("cp.async.cg.shared.global [%0], [%1], 16;" :: "r"(s), "l"(g));
}
__device__ __forceinline__ void cpa_commit() {
    asm volatile("cp.async.commit_group;" ::: "memory");
}
__device__ __forceinline__ void ldsm4(uint32_t* r, uint32_t a) {
    asm volatile("ldmatrix.sync.aligned.m8n8.x4.shared.b16 {%0,%1,%2,%3}, [%4];"
                 : "=r"(r[0]), "=r"(r[1]), "=r"(r[2]), "=r"(r[3]) : "r"(a));
}
__device__ __forceinline__ void ldsm2(uint32_t* r, uint32_t a) {
    asm volatile("ldmatrix.sync.aligned.m8n8.x2.shared.b16 {%0,%1}, [%2];"
                 : "=r"(r[0]), "=r"(r[1]) : "r"(a));
}
__device__ __forceinline__ void mma_bf16(float* c, const uint32_t* a, const uint32_t* b) {
    asm volatile(
        "mma.sync.aligned.m16n8k16.row.col.f32.bf16.bf16.f32 "
        "{%0,%1,%2,%3}, {%4,%5,%6,%7}, {%8,%9}, {%0,%1,%2,%3};"
        : "+f"(c[0]), "+f"(c[1]), "+f"(c[2]), "+f"(c[3])
        : "r"(a[0]), "r"(a[1]), "r"(a[2]), "r"(a[3]), "r"(b[0]), "r"(b[1]));
}
__device__ __forceinline__ void mma_f16(float* c, const uint32_t* a, const uint32_t* b) {
    asm volatile(
        "mma.sync.aligned.m16n8k16.row.col.f32.f16.f16.f32 "
        "{%0,%1,%2,%3}, {%4,%5,%6,%7}, {%8,%9}, {%0,%1,%2,%3};"
        : "+f"(c[0]), "+f"(c[1]), "+f"(c[2]), "+f"(c[3])
        : "r"(a[0]), "r"(a[1]), "r"(a[2]), "r"(a[3]), "r"(b[0]), "r"(b[1]));
}
__device__ __forceinline__ void split2bf(float x, float y, uint32_t& hi, uint32_t& lo) {
    __nv_bfloat162 h = __floats2bfloat162_rn(x, y);
    float hx = __bfloat162float(h.x), hy = __bfloat162float(h.y);
    __nv_bfloat162 l = __floats2bfloat162_rn(x - hx, y - hy);
    hi = *reinterpret_cast<uint32_t*>(&h);
    lo = *reinterpret_cast<uint32_t*>(&l);
}

// ============================================================================
// fp16 split kernels
// ============================================================================
// amode=1 -> [hi, lo]; amode=0 -> [hi, hi]
__global__ void split_kernel_h(const float* __restrict__ src,
                               __half* __restrict__ dst,
                               int K, int dstStride, int dstOff, int amode, int n)
{
    int i = blockIdx.x * 256 + threadIdx.x;
    if (i >= n) return;
    int r = i / K, k = i % K;
    float x = src[i];
    __half hi = __float2half_rn(x);
    __half sec = amode ? __float2half_rn(x - __half2float(hi)) : hi;
    __half* d = dst + (size_t)r * dstStride + dstOff;
    d[k] = hi;
    d[K + k] = sec;
}

// fused concat(enc,hid) + A-split
__global__ void split_concat_kernel(const float* __restrict__ hid,
                                    const float* __restrict__ enc)
{
    int i = blockIdx.x * 256 + threadIdx.x;
    if (i >= S_TOT * DMODEL) return;
    int r = i / DMODEL, k = i % DMODEL;
    float x = (r < TLEN) ? enc[i] : hid[i - TLEN * DMODEL];
    __half hi = __float2half_rn(x);
    __half lo = __float2half_rn(x - __half2float(hi));
    __half* d = g_ab + (size_t)r * K2;
    d[k] = hi;
    d[DMODEL + k] = lo;
}

// split fp32 A (attn out) into g_ab
__global__ void split_a_kernel(const float* __restrict__ src)
{
    int i = blockIdx.x * 256 + threadIdx.x;
    if (i >= S_TOT * DMODEL) return;
    int r = i / DMODEL, k = i % DMODEL;
    float x = src[i];
    __half hi = __float2half_rn(x);
    __half lo = __float2half_rn(x - __half2float(hi));
    __half* d = g_ab + (size_t)r * K2;
    d[k] = hi;
    d[DMODEL + k] = lo;
}

// t-split: g_t[2048][nproj*128] -> g_tb[2048][768], per-proj contiguous [hi|lo]
__global__ void tsplit_kernel(int nproj)
{
    int n = S_TOT * nproj * RANK_;
    int i = blockIdx.x * 256 + threadIdx.x;
    if (i >= n) return;
    int kw = nproj * RANK_;
    int r = i / kw, k = i % kw;
    int p = k >> 7, kk = k & 127;
    float x = g_t[(size_t)r * kw + k];
    __half hi = __float2half_rn(x);
    __half lo = __float2half_rn(x - __half2float(hi));
    __half* d = g_tb + (size_t)r * 768 + p * 256;
    d[kk] = hi;
    d[128 + kk] = lo;
}

// ============================================================================
// HMMA NT GEMM, BK=64, two-source A (main + tail), optional permuted store.
//   chunk c < h_chunks : A from Ah (lda_h), col = kbase + c*64
//   chunk c >= h_chunks: A from At (lda_t), col = toff + (c-h_chunks)*64
// B column = kbase + c*64 (split-K moves through B as well).
// ============================================================================
#define GEMM_SMEM (4 * 128 * 72 * 2)   // 73728 bytes: A/B x 2 stages, 144B rows

__global__ void __launch_bounds__(256) gemm_hmma(
    const __half* __restrict__ Ah, int lda_h, int h_chunks,
    const __half* __restrict__ At, int lda_t, int toff,
    const __half* __restrict__ B, int ldb,
    const float* __restrict__ bias, float* __restrict__ C, int ldc,
    int chunks, int use_atomic, int permute)
{
    extern __shared__ __half sm[];
    __half* smA = sm;                     // [2][128*72]
    __half* smB = sm + 2 * 128 * 72;      // [2][128*72]

    const int tid = threadIdx.x;
    const int lane = tid & 31;
    const int wid = tid >> 5;
    const int wm0 = (wid & 1) * 64;
    const int wn0 = (wid >> 1) * 32;
    const int r0 = blockIdx.y << 7;
    const int c0 = blockIdx.x << 7;
    const int kbase = blockIdx.z * chunks * 64;

    float acc[4][4][4];
#pragma unroll
    for (int i = 0; i < 4; i++)
#pragma unroll
        for (int j = 0; j < 4; j++)
#pragma unroll
            for (int e = 0; e < 4; e++) acc[i][j][e] = 0.f;

    const int lrow = tid >> 3;            // 0..31 (with i-loop -> 0..127)
    const int lch = tid & 7;              // 16B chunk within 128B row

    auto load_tile = [&](int c) {
        int b = c & 1;
        uint32_t sa = s2u(smA) + b * (128 * 144) + lrow * 144 + lch * 16;
        uint32_t sb = s2u(smB) + b * (128 * 144) + lrow * 144 + lch * 16;
        const __half* ga;
        int alda;
        if (c < h_chunks) { ga = Ah + kbase + c * 64 + lch * 8; alda = lda_h; }
        else              { ga = At + toff + (c - h_chunks) * 64 + lch * 8; alda = lda_t; }
        const __half* gb = B + (size_t)c0 * ldb + kbase + c * 64 + lch * 8;
#pragma unroll
        for (int i = 0; i < 4; i++) {
            int row = lrow + i * 32;
            cpa16(sa + i * (32 * 144), ga + (size_t)(r0 + row) * alda);
            cpa16(sb + i * (32 * 144), gb + (size_t)row * ldb);
        }
        cpa_commit();
    };

    load_tile(0);

    for (int c = 0; c < chunks; c++) {
        if (c + 1 < chunks) {
            load_tile(c + 1);
            asm volatile("cp.async.wait_group 1;" ::: "memory");
        } else {
            asm volatile("cp.async.wait_group 0;" ::: "memory");
        }
        __syncthreads();

        int b = c & 1;
        uint32_t saw = s2u(smA) + b * (128 * 144)
                       + (uint32_t)((wm0 + (lane & 15)) * 144) + ((lane >> 4) << 4);
        uint32_t sbw = s2u(smB) + b * (128 * 144)
                       + (uint32_t)((wn0 + (lane & 7)) * 144) + (((lane >> 3) & 1) << 4);
#pragma unroll
        for (int s = 0; s < 4; s++) {
            uint32_t af[4][4], bf[4][2];
#pragma unroll
            for (int i = 0; i < 4; i++) ldsm4(af[i], saw + i * (16 * 144) + s * 32);
#pragma unroll
            for (int j = 0; j < 4; j++) ldsm2(bf[j], sbw + j * (8 * 144) + s * 32);
#pragma unroll
            for (int i = 0; i < 4; i++)
#pragma unroll
                for (int j = 0; j < 4; j++)
                    mma_f16(acc[i][j], af[i], bf[j]);
        }
        __syncthreads();
    }

#pragma unroll
    for (int i = 0; i < 4; i++) {
#pragma unroll
        for (int j = 0; j < 4; j++) {
            int mm = r0 + wm0 + i * 16 + (lane >> 2);
            int nn = c0 + wn0 + j * 8 + (lane & 3) * 2;
            int row0 = mm, row1 = mm + 8;
            if (permute) {
                row0 = (row0 < TLEN) ? row0 + VLEN : row0 - TLEN;
                row1 = (row1 < TLEN) ? row1 + VLEN : row1 - TLEN;
            }
            float* p0 = C + (size_t)row0 * ldc + nn;
            float* p1 = C + (size_t)row1 * ldc + nn;
            if (use_atomic) {
                atomicAdd(p0,     acc[i][j][0]);
                atomicAdd(p0 + 1, acc[i][j][1]);
                atomicAdd(p1,     acc[i][j][2]);
                atomicAdd(p1 + 1, acc[i][j][3]);
            } else {
                float b0v = bias ? bias[nn] : 0.f;
                float b1v = bias ? bias[nn + 1] : 0.f;
                p0[0] = acc[i][j][0] + b0v;
                p0[1] = acc[i][j][1] + b1v;
                p1[0] = acc[i][j][2] + b0v;
                p1[1] = acc[i][j][3] + b1v;
            }
        }
    }
}

// ============================================================================
// LN(64) + RoPE -> bf16 hi/lo planes, head-major
// ============================================================================
__global__ void ln_rope_split(const float* __restrict__ x,
                              const float* __restrict__ gamma,
                              const float* __restrict__ beta,
                              const float* __restrict__ cosb,
                              const float* __restrict__ sinb,
                              __nv_bfloat16* __restrict__ hi_out,
                              __nv_bfloat16* __restrict__ lo_out,
                              float qscale)
{
    int gw = (blockIdx.x * blockDim.x + threadIdx.x) >> 5;
    int lane = threadIdx.x & 31;
    if (gw >= S_TOT * NHEADS) return;
    int pos = gw / NHEADS, head = gw % NHEADS;
    const float* row = x + (size_t)pos * DMODEL + head * HDIM;

    float2 v = ((const float2*)row)[lane];
    float sum = v.x + v.y;
#pragma unroll
    for (int o = 16; o; o >>= 1) sum += __shfl_xor_sync(0xffffffffu, sum, o);
    float mu = sum * (1.f / 64.f);
    float dx = v.x - mu, dy = v.y - mu;
    float vs = dx * dx + dy * dy;
#pragma unroll
    for (int o = 16; o; o >>= 1) vs += __shfl_xor_sync(0xffffffffu, vs, o);
    float inv = rsqrtf(vs * (1.f / 64.f) + 1e-5f);

    float y0 = dx * inv * gamma[lane * 2]     + beta[lane * 2];
    float y1 = dy * inv * gamma[lane * 2 + 1] + beta[lane * 2 + 1];

    if (pos >= TLEN) {
        int r = pos - TLEN;
        float c0 = cosb[r * HDIM + lane * 2], c1 = cosb[r * HDIM + lane * 2 + 1];
        float s0 = sinb[r * HDIM + lane * 2], s1 = sinb[r * HDIM + lane * 2 + 1];
        float t0 = y0 * c0 - y1 * s0;
        float t1 = y1 * c1 + y0 * s1;
        y0 = t0; y1 = t1;
    }
    y0 *= qscale; y1 *= qscale;

    size_t base = ((size_t)head * S_TOT + pos) * HDIM;
    uint32_t hi, lo;
    split2bf(y0, y1, hi, lo);
    *reinterpret_cast<uint32_t*>(hi_out + base + lane * 2) = hi;
    *reinterpret_cast<uint32_t*>(lo_out + base + lane * 2) = lo;
}

// ============================================================================
// V transpose + split (bf16)
// ============================================================================
__global__ void vt_split()
{
    __shared__ float tile[64][65];
    int head = blockIdx.y, p0 = blockIdx.x * 64;
    int tid = threadIdx.x;
#pragma unroll
    for (int i = 0; i < 16; i++) {
        int idx = tid + i * 256;
        int p = idx >> 6, d = idx & 63;
        tile[p][d] = g_v[(size_t)(p0 + p) * DMODEL + head * HDIM + d];
    }
    __syncthreads();
#pragma unroll
    for (int i = 0; i < 16; i++) {
        int idx = tid + i * 256;
        int d = idx >> 6, p = idx & 63;
        float x = tile[p][d];
        __nv_bfloat16 hi = __float2bfloat16(x);
        __nv_bfloat16 lo = __float2bfloat16(x - __bfloat162float(hi));
        size_t o = ((size_t)head * HDIM + d) * S_TOT + p0 + p;
        g_vthi[o] = hi;
        g_vtlo[o] = lo;
    }
}

// ============================================================================
// HMMA flash attention (bf16 3-term)
// ============================================================================
#define ATT_SQH 0
#define ATT_SQL 18432
#define ATT_SK  36864
#define ATT_SV  110592
#define ATT_SMEM 180224

__global__ void __launch_bounds__(256) attn_hmma()
{
    extern __shared__ char smc[];
    const int head = blockIdx.y;
    const int q0 = blockIdx.x * 128;
    const int tid = threadIdx.x;
    const int lane = tid & 31;
    const int wid = tid >> 5;

    const uint32_t smb = s2u(smc);

    {
        const __nv_bfloat16* Qh = g_qhi + ((size_t)head * S_TOT + q0) * HDIM;
        const __nv_bfloat16* Ql = g_qlo + ((size_t)head * S_TOT + q0) * HDIM;
#pragma unroll
        for (int i = 0; i < 4; i++) {
            int idx = tid + i * 256;
            int row = idx >> 3, ch = idx & 7;
            cpa16(smb + ATT_SQH + row * 144 + ch * 16, Qh + row * HDIM + ch * 8);
            cpa16(smb + ATT_SQL + row * 144 + ch * 16, Ql + row * HDIM + ch * 8);
        }
        cpa_commit();
    }

    auto load_kv = [&](int c) {
        int buf = c & 1;
        const __nv_bfloat16* Kh = g_khi + ((size_t)head * S_TOT + c * 128) * HDIM;
        const __nv_bfloat16* Kl = g_klo + ((size_t)head * S_TOT + c * 128) * HDIM;
        uint32_t kb = smb + ATT_SK + buf * 36864;
#pragma unroll
        for (int i = 0; i < 4; i++) {
            int idx = tid + i * 256;
            int row = idx >> 3, ch = idx & 7;
            cpa16(kb + row * 144 + ch * 16, Kh + row * HDIM + ch * 8);
            cpa16(kb + 18432 + row * 144 + ch * 16, Kl + row * HDIM + ch * 8);
        }
        const __nv_bfloat16* Vh = g_vthi + (size_t)head * HDIM * S_TOT + c * 128;
        const __nv_bfloat16* Vl = g_vtlo + (size_t)head * HDIM * S_TOT + c * 128;
        uint32_t vb = smb + ATT_SV + buf * 34816;
#pragma unroll
        for (int i = 0; i < 4; i++) {
            int idx = tid + i * 256;
            int d = idx >> 4, ch = idx & 15;
            cpa16(vb + d * 272 + ch * 16, Vh + (size_t)d * S_TOT + ch * 8);
            cpa16(vb + 17408 + d * 272 + ch * 16, Vl + (size_t)d * S_TOT + ch * 8);
        }
        cpa_commit();
    };

    load_kv(0);

    uint32_t aQh[4][4], aQl[4][4];
    float O[8][4];
#pragma unroll
    for (int j = 0; j < 8; j++)
#pragma unroll
        for (int e = 0; e < 4; e++) O[j][e] = 0.f;
    float m0 = -1e30f, m1 = -1e30f, l0 = 0.f, l1 = 0.f;

    for (int c = 0; c < S_TOT / 128; c++) {
        if (c + 1 < S_TOT / 128) {
            load_kv(c + 1);
            asm volatile("cp.async.wait_group 1;" ::: "memory");
        } else {
            asm volatile("cp.async.wait_group 0;" ::: "memory");
        }
        __syncthreads();

        if (c == 0) {
            uint32_t qa = smb + (uint32_t)((wid * 16 + (lane & 15)) * 144)
                          + ((lane >> 4) << 4);
#pragma unroll
            for (int kc = 0; kc < 4; kc++) {
                ldsm4(aQh[kc], qa + ATT_SQH + kc * 32);
                ldsm4(aQl[kc], qa + ATT_SQL + kc * 32);
            }
        }

        int buf = c & 1;
        float s[16][4];
#pragma unroll
        for (int j = 0; j < 16; j++)
#pragma unroll
            for (int e = 0; e < 4; e++) s[j][e] = 0.f;

        uint32_t kb = smb + ATT_SK + buf * 36864 + (uint32_t)((lane & 7) * 144)
                      + (((lane >> 3) & 1) << 4);
#pragma unroll
        for (int kc = 0; kc < 4; kc++) {
#pragma unroll
            for (int j = 0; j < 16; j++) {
                uint32_t bh[2], bl[2];
                uint32_t a = kb + j * (8 * 144) + kc * 32;
                ldsm2(bh, a);
                mma_bf16(s[j], aQh[kc], bh);
                mma_bf16(s[j], aQl[kc], bh);
                ldsm2(bl, a + 18432);
                mma_bf16(s[j], aQh[kc], bl);
            }
        }

        float mx0 = -1e30f, mx1 = -1e30f;
#pragma unroll
        for (int j = 0; j < 16; j++) {
            mx0 = fmaxf(mx0, fmaxf(s[j][0], s[j][1]));
            mx1 = fmaxf(mx1, fmaxf(s[j][2], s[j][3]));
        }
        mx0 = fmaxf(mx0, __shfl_xor_sync(0xffffffffu, mx0, 1));
        mx0 = fmaxf(mx0, __shfl_xor_sync(0xffffffffu, mx0, 2));
        mx1 = fmaxf(mx1, __shfl_xor_sync(0xffffffffu, mx1, 1));
        mx1 = fmaxf(mx1, __shfl_xor_sync(0xffffffffu, mx1, 2));
        float mn0 = fmaxf(m0, mx0), mn1 = fmaxf(m1, mx1);
        float cr0 = __expf(m0 - mn0), cr1 = __expf(m1 - mn1);
        m0 = mn0; m1 = mn1;

        float rs0 = 0.f, rs1 = 0.f;
#pragma unroll
        for (int j = 0; j < 16; j++) {
            s[j][0] = __expf(s[j][0] - mn0);
            s[j][1] = __expf(s[j][1] - mn0);
            s[j][2] = __expf(s[j][2] - mn1);
            s[j][3] = __expf(s[j][3] - mn1);
            rs0 += s[j][0] + s[j][1];
            rs1 += s[j][2] + s[j][3];
        }
        rs0 += __shfl_xor_sync(0xffffffffu, rs0, 1);
        rs0 += __shfl_xor_sync(0xffffffffu, rs0, 2);
        rs1 += __shfl_xor_sync(0xffffffffu, rs1, 1);
        rs1 += __shfl_xor_sync(0xffffffffu, rs1, 2);
        l0 = l0 * cr0 + rs0;
        l1 = l1 * cr1 + rs1;

#pragma unroll
        for (int j = 0; j < 8; j++) {
            O[j][0] *= cr0; O[j][1] *= cr0;
            O[j][2] *= cr1; O[j][3] *= cr1;
        }

        uint32_t vb = smb + ATT_SV + buf * 34816 + (uint32_t)((lane & 7) * 272)
                      + (((lane >> 3) & 1) << 4);
#pragma unroll
        for (int ck = 0; ck < 8; ck++) {
            uint32_t ah[4], al[4];
            split2bf(s[2 * ck][0],     s[2 * ck][1],     ah[0], al[0]);
            split2bf(s[2 * ck][2],     s[2 * ck][3],     ah[1], al[1]);
            split2bf(s[2 * ck + 1][0], s[2 * ck + 1][1], ah[2], al[2]);
            split2bf(s[2 * ck + 1][2], s[2 * ck + 1][3], ah[3], al[3]);
#pragma unroll
            for (int jd = 0; jd < 8; jd++) {
                uint32_t bh[2], bl[2];
                uint32_t a = vb + jd * (8 * 272) + ck * 32;
                ldsm2(bh, a);
                mma_bf16(O[jd], ah, bh);
                mma_bf16(O[jd], al, bh);
                ldsm2(bl, a + 17408);
                mma_bf16(O[jd], ah, bl);
            }
        }
        __syncthreads();
    }

    float i0 = 1.f / l0, i1 = 1.f / l1;
    int r = q0 + wid * 16 + (lane >> 2);
    int cb = head * HDIM + (lane & 3) * 2;
#pragma unroll
    for (int jd = 0; jd < 8; jd++) {
        float* p0 = g_attn + (size_t)r * DMODEL + cb + jd * 8;
        float* p1 = g_attn + (size_t)(r + 8) * DMODEL + cb + jd * 8;
        p0[0] = O[jd][0] * i0; p0[1] = O[jd][1] * i0;
        p1[0] = O[jd][2] * i1; p1[1] = O[jd][3] * i1;
    }
}

// ============================================================================
extern "C" void kernel_launch(void* const* d_in, const int* in_sizes, int n_in,
                              void* d_out, int out_size)
{
    const float* hid = (const float*)d_in[0];
    const float* enc = (const float*)d_in[1];
    const float* rc  = (const float*)d_in[2];
    const float* rs  = (const float*)d_in[3];
    const float* Wq  = (const float*)d_in[4];  const float* bq = (const float*)d_in[5];
    const float* Wk  = (const float*)d_in[6];  const float* bk = (const float*)d_in[7];
    const float* Wv  = (const float*)d_in[8];  const float* bv = (const float*)d_in[9];
    const float* Wo  = (const float*)d_in[10]; const float* bo = (const float*)d_in[11];
    const float* lqd = (const float*)d_in[12]; const float* lqu = (const float*)d_in[13];
    const float* lkd = (const float*)d_in[14]; const float* lku = (const float*)d_in[15];
    const float* lvd = (const float*)d_in[16]; const float* lvu = (const float*)d_in[17];
    const float* lpd = (const float*)d_in[18]; const float* lpu = (const float*)d_in[19];
    const float* gq  = (const float*)d_in[20]; const float* btq = (const float*)d_in[21];
    const float* gk  = (const float*)d_in[22]; const float* btk = (const float*)d_in[23];

    static int attr_done = 0;
    if (!attr_done) {
        cudaFuncSetAttribute(attn_hmma, cudaFuncAttributeMaxDynamicSharedMemorySize,
                             ATT_SMEM);
        cudaFuncSetAttribute(gemm_hmma, cudaFuncAttributeMaxDynamicSharedMemorySize,
                             GEMM_SMEM);
        attr_done = 1;
    }

    float *pq, *pk, *pv, *pt, *pa;
    __half *pab, *ptb, *pldb;
    __half* pwb[3];
    __nv_bfloat16 *pqh, *pql, *pkh, *pkl;
    cudaGetSymbolAddress((void**)&pq, g_q);
    cudaGetSymbolAddress((void**)&pk, g_k);
    cudaGetSymbolAddress((void**)&pv, g_v);
    cudaGetSymbolAddress((void**)&pt, g_t);
    cudaGetSymbolAddress((void**)&pa, g_attn);
    cudaGetSymbolAddress((void**)&pab, g_ab);
    cudaGetSymbolAddress((void**)&ptb, g_tb);
    cudaGetSymbolAddress((void**)&pldb, g_ldb);
    {
        __half* base;
        cudaGetSymbolAddress((void**)&base, g_wb);
        for (int p = 0; p < 3; p++) pwb[p] = base + (size_t)p * DMODEL * LDB_BIG;
    }
    cudaGetSymbolAddress((void**)&pqh, g_qhi);
    cudaGetSymbolAddress((void**)&pql, g_qlo);
    cudaGetSymbolAddress((void**)&pkh, g_khi);
    cudaGetSymbolAddress((void**)&pkl, g_klo);

    const int nHD = S_TOT * DMODEL;
    const int nW  = DMODEL * DMODEL;
    const int nLD = RANK_ * DMODEL;
    const int nLU = DMODEL * RANK_;

    dim3 big_grid(DMODEL / 128, S_TOT / 128, 1);     // 24 x 16
    dim3 lora3_grid(3, S_TOT / 128, 8);              // N=384, split-K 8
    dim3 lora1_grid(1, S_TOT / 128, 8);              // N=128, split-K 8
    const int LORA_CH = H_CHUNKS / 8;                // 12

    // ---- A operand (h) + all weight splits up front ----
    split_concat_kernel<<<(nHD + 255) / 256, 256>>>(hid, enc);
    const float* Ws[3]  = {Wq, Wk, Wv};
    const float* lus[3] = {lqu, lku, lvu};
    const float* lds[3] = {lqd, lkd, lvd};
    for (int p = 0; p < 3; p++) {
        split_kernel_h<<<(nW + 255) / 256, 256>>>(Ws[p], pwb[p], DMODEL, LDB_BIG, 0, 0, nW);
        split_kernel_h<<<(nLU + 255) / 256, 256>>>(lus[p], pwb[p], RANK_, LDB_BIG, K2, 0, nLU);
        split_kernel_h<<<(nLD + 255) / 256, 256>>>(lds[p], pldb + (size_t)(p * RANK_) * K2,
                                                   DMODEL, K2, 0, 0, nLD);
    }

    // ---- batched lora-down for q,k,v: t[2048x384] ----
    cudaMemsetAsync(pt, 0, S_TOT * 3 * RANK_ * sizeof(float));
    gemm_hmma<<<lora3_grid, 256, GEMM_SMEM>>>(pab, K2, H_CHUNKS, nullptr, 0, 0,
                                              pldb, K2, nullptr, pt, 3 * RANK_,
                                              LORA_CH, 1, 0);
    tsplit_kernel<<<(S_TOT * 3 * RANK_ + 255) / 256, 256>>>(3);

    // ---- three big GEMMs back-to-back ----
    float* outs[3] = {pq, pk, pv};
    const float* bs[3] = {bq, bk, bv};
    for (int p = 0; p < 3; p++) {
        gemm_hmma<<<big_grid, 256, GEMM_SMEM>>>(pab, K2, H_CHUNKS, ptb, 768, p * 256,
                                                pwb[p], LDB_BIG, bs[p], outs[p], DMODEL,
                                                BIG_CHUNKS, 0, 0);
    }

    // ---- LN + RoPE -> bf16 split planes ----
    int ln_blocks = (S_TOT * NHEADS * 32 + 255) / 256;
    ln_rope_split<<<ln_blocks, 256>>>(pq, gq, btq, rc, rs, pqh, pql, 0.125f);
    ln_rope_split<<<ln_blocks, 256>>>(pk, gk, btk, rc, rs, pkh, pkl, 1.0f);
    vt_split<<<dim3(S_TOT / 64, NHEADS), 256>>>();

    attn_hmma<<<dim3(S_TOT / 128, NHEADS), 256, ATT_SMEM>>>();

    // ---- output projection (fused permute into epilogue) ----
    split_a_kernel<<<(nHD + 255) / 256, 256>>>(pa);
    split_kernel_h<<<(nW + 255) / 256, 256>>>(Wo, pwb[0], DMODEL, LDB_BIG, 0, 0, nW);
    split_kernel_h<<<(nLU + 255) / 256, 256>>>(lpu, pwb[0], RANK_, LDB_BIG, K2, 0, nLU);
    split_kernel_h<<<(nLD + 255) / 256, 256>>>(lpd, pldb, DMODEL, K2, 0, 0, nLD);
    cudaMemsetAsync(pt, 0, S_TOT * RANK_ * sizeof(float));
    gemm_hmma<<<lora1_grid, 256, GEMM_SMEM>>>(pab, K2, H_CHUNKS, nullptr, 0, 0,
                                              pldb, K2, nullptr, pt, RANK_,
                                              LORA_CH, 1, 0);
    tsplit_kernel<<<(S_TOT * RANK_ + 255) / 256, 256>>>(1);
    gemm_hmma<<<big_grid, 256, GEMM_SMEM>>>(pab, K2, H_CHUNKS, ptb, 768, 0,
                                            pwb[0], LDB_BIG, bo, (float*)d_out, DMODEL,
                                            BIG_CHUNKS, 0, 1);
}